// round 13
// baseline (speedup 1.0000x reference)
#include <cuda_runtime.h>
#include <cuda_fp16.h>
#include <math.h>

#define BN 2
#define TN 2048
#define HN 1024
#define DN 64
#define MN 16
#define QKV_ELEMS (BN*MN*TN*DN)
typedef unsigned long long u64;
typedef unsigned int u32;

__device__ __forceinline__ void mma16(float* d, u32 a0, u32 a1, u32 a2, u32 a3, u32 b0, u32 b1){
    asm volatile("mma.sync.aligned.m16n8k16.row.col.f32.f16.f16.f32 "
        "{%0,%1,%2,%3},{%4,%5,%6,%7},{%8,%9},{%0,%1,%2,%3};"
        : "+f"(d[0]),"+f"(d[1]),"+f"(d[2]),"+f"(d[3])
        : "r"(a0),"r"(a1),"r"(a2),"r"(a3),"r"(b0),"r"(b1));
}
__device__ __forceinline__ void packpair(float v0, float v1, u32& hi, u32& lo){
    __half h0 = __float2half_rn(v0), h1 = __float2half_rn(v1);
    __half2 H = __halves2half2(h0, h1);
    __half2 L = __halves2half2(__float2half_rn(v0 - __half2float(h0)),
                               __float2half_rn(v1 - __half2float(h1)));
    hi = *(u32*)&H; lo = *(u32*)&L;
}
__device__ __forceinline__ u32 packhi(float v0, float v1){
    __half2 H = __halves2half2(__float2half_rn(v0), __float2half_rn(v1));
    return *(u32*)&H;
}
__device__ __forceinline__ int pidx(int p){
    return ((p>>3)<<4) + ((p&3)<<2) + (((p>>2)&1)<<1);
}
__device__ __forceinline__ u64 pk2f(float lo, float hi){
    u64 r; asm("mov.b64 %0, {%1,%2};" : "=l"(r) : "f"(lo), "f"(hi)); return r;
}
__device__ __forceinline__ void upk2f(float& lo, float& hi, u64 v){
    asm("mov.b64 {%0,%1}, %2;" : "=f"(lo), "=f"(hi) : "l"(v));
}
__device__ __forceinline__ void ffma2(u64& d, u64 a, u64 b){
    asm("fma.rn.f32x2 %0, %1, %2, %0;" : "+l"(d) : "l"(a), "l"(b));
}
__device__ __forceinline__ u32 s2u(const void* p){
    u32 a; asm("{ .reg .u64 t; cvta.to.shared.u64 t, %1; cvt.u32.u64 %0, t; }":"=r"(a):"l"(p)); return a;
}
__device__ __forceinline__ void cpa16(u32 dst, const void* src){
    asm volatile("cp.async.cg.shared.global [%0], [%1], 16;" :: "r"(dst), "l"(src) : "memory");
}
#define CPA_COMMIT() asm volatile("cp.async.commit_group;" ::: "memory")
#define CPA_WAIT1()  asm volatile("cp.async.wait_group 1;" ::: "memory")
#define CPA_WAIT0()  asm volatile("cp.async.wait_group 0;" ::: "memory")

__device__ u32   g_hsp[BN*TN*1024];
__device__ u32   g_wp[3*MN*64*1024];
__device__ u32   g_qp[BN*MN*TN*64];
__device__ u32   g_kp[BN*MN*TN*64];
__device__ float g_v[QKV_ELEMS];
__device__ u32   g_vp[BN*MN*64*2048];
__device__ double g_ent[BN*MN];
__device__ float g_nmask[BN*MN];
__device__ float g_comb[BN*TN*DN];
__device__ float g_oproj[BN*DN*HN];

#define OFF_SHA   (BN*TN*HN)
#define OFF_LOGIT (OFF_SHA + BN*TN*MN*DN)
#define OFF_MASK  (OFF_LOGIT + BN*MN)
#define OFF_FBC   (OFF_MASK + BN*MN)

__global__ void init_kernel(){ g_ent[threadIdx.x] = 0.0; }

__global__ void split_hs_kernel(const float* __restrict__ hs){
    int row = blockIdx.x, t = threadIdx.x;
    float4 v = *(const float4*)(hs + (size_t)row*1024 + t*4);
    u32 hi, lo;
    u32* O = g_hsp + (size_t)row*1024;
    packpair(v.x, v.y, hi, lo); *(u64*)(O + pidx(2*t))   = (u64)hi | ((u64)lo<<32);
    packpair(v.z, v.w, hi, lo); *(u64*)(O + pidx(2*t+1)) = (u64)hi | ((u64)lo<<32);
}
__global__ void split_w_kernel(const float* __restrict__ wq, const float* __restrict__ wk,
                               const float* __restrict__ wv){
    int which = blockIdx.y;
    const float* W = which==0 ? wq : which==1 ? wk : wv;
    int flat = blockIdx.x*256 + threadIdx.x;
    int mx = flat >> 13, r = flat & 8191, p = r >> 4, d4 = (r & 15) * 4;
    const float* Wm = W + (size_t)mx*HN*DN;
    float4 va = *(const float4*)(Wm + (size_t)(2*p)*DN + d4);
    float4 vb = *(const float4*)(Wm + (size_t)(2*p+1)*DN + d4);
    u32* O = g_wp + (size_t)(which*MN + mx)*64*1024;
    float a[4] = {va.x, va.y, va.z, va.w}, bq[4] = {vb.x, vb.y, vb.z, vb.w};
    int ix = pidx(p);
    #pragma unroll
    for (int e = 0; e < 4; e++){
        u32 hi, lo; packpair(a[e], bq[e], hi, lo);
        *(u64*)(O + (size_t)(d4+e)*1024 + ix) = (u64)hi | ((u64)lo<<32);
    }
}
__global__ void repack_v_kernel(){
    int flat = blockIdx.x*256 + threadIdx.x;
    int bm = blockIdx.y;
    int p = flat >> 4, d4 = (flat & 15) * 4;
    const float* V = g_v + (size_t)bm*TN*64;
    float4 va = *(const float4*)(V + (size_t)(2*p)*64 + d4);
    float4 vb = *(const float4*)(V + (size_t)(2*p+1)*64 + d4);
    u32* O = g_vp + (size_t)bm*64*2048;
    float a[4] = {va.x, va.y, va.z, va.w}, bq[4] = {vb.x, vb.y, vb.z, vb.w};
    int ix = pidx(p);
    #pragma unroll
    for (int e = 0; e < 4; e++){
        u32 hi, lo; packpair(a[e], bq[e], hi, lo);
        *(u64*)(O + (size_t)(d4+e)*2048 + ix) = (u64)hi | ((u64)lo<<32);
    }
}

// ===== proj: 256 thr (8 warps), CTA tile 256t x 64d, R=2, 32-k stages =====
#define PJ_STG (256*36 + 64*36)        // 11520 u32 per stage
#define PJ_SMEM (PJ_STG*2*4)           // 92160 B
__global__ void __launch_bounds__(256,2) proj_kernel(){
    extern __shared__ u32 smu[];
    int tid = threadIdx.x, w = tid>>5, lane = tid&31, grp = lane>>2, tc = lane&3, rb = w*32;
    int qt = blockIdx.x, mx = blockIdx.y, b = blockIdx.z/3, which = blockIdx.z%3;
    const u32* Ag = g_hsp + (size_t)(b*TN + qt*256)*1024;
    const u32* Wg = g_wp + (size_t)(which*MN + mx)*64*1024;
    u32 sbase = s2u(smu);

    {
        u32 bA = sbase, bW = sbase + 256*36*4;
        #pragma unroll
        for (int j = 0; j < 8; j++){ int u = j*256+tid, row = u>>3, q = (u&7)*4;
            cpa16(bA + (row*36 + q)*4, Ag + (size_t)row*1024 + q); }
        #pragma unroll
        for (int j = 0; j < 2; j++){ int u = j*256+tid, row = u>>3, q = (u&7)*4;
            cpa16(bW + (row*36 + q)*4, Wg + (size_t)row*1024 + q); }
        CPA_COMMIT();
    }

    float c[2][8][4] = {};
    for (int st = 0; st < 32; st++){
        __syncthreads();
        if (st+1 < 32){
            u32 bA = sbase + ((st+1)&1)*PJ_STG*4, bW = bA + 256*36*4;
            int off = (st+1)*32;
            #pragma unroll
            for (int j = 0; j < 8; j++){ int u = j*256+tid, row = u>>3, q = (u&7)*4;
                cpa16(bA + (row*36 + q)*4, Ag + (size_t)row*1024 + off + q); }
            #pragma unroll
            for (int j = 0; j < 2; j++){ int u = j*256+tid, row = u>>3, q = (u&7)*4;
                cpa16(bW + (row*36 + q)*4, Wg + (size_t)row*1024 + off + q); }
            CPA_COMMIT();
            CPA_WAIT1();
        } else {
            CPA_WAIT0();
        }
        __syncthreads();
        u32* sA = smu + (st&1)*PJ_STG;
        u32* sW = sA + 256*36;
        #pragma unroll
        for (int kc = 0; kc < 2; kc++){
            uint4 A0[2], A1[2];
            #pragma unroll
            for (int i = 0; i < 2; i++){
                A0[i] = *(uint4*)(sA + (rb+16*i+grp)*36 + kc*16 + tc*4);
                A1[i] = *(uint4*)(sA + (rb+16*i+grp+8)*36 + kc*16 + tc*4);
            }
            #pragma unroll
            for (int nt = 0; nt < 8; nt++){
                uint4 bb = *(uint4*)(sW + (nt*8+grp)*36 + kc*16 + tc*4);
                #pragma unroll
                for (int i = 0; i < 2; i++){
                    mma16(c[i][nt], A0[i].x, A1[i].x, A0[i].z, A1[i].z, bb.x, bb.z);
                    mma16(c[i][nt], A0[i].x, A1[i].x, A0[i].z, A1[i].z, bb.y, bb.w);
                    mma16(c[i][nt], A0[i].y, A1[i].y, A0[i].w, A1[i].w, bb.x, bb.z);
                }
            }
        }
    }
    size_t rowbase = (size_t)(b*MN + mx)*TN + (size_t)qt*256;
    if (which == 2){
        #pragma unroll
        for (int i = 0; i < 2; i++)
            #pragma unroll
            for (int nt = 0; nt < 8; nt++){
                int col = nt*8 + 2*tc;
                *(float2*)(g_v + (rowbase + rb+16*i+grp)*64 + col)   = make_float2(c[i][nt][0], c[i][nt][1]);
                *(float2*)(g_v + (rowbase + rb+16*i+grp+8)*64 + col) = make_float2(c[i][nt][2], c[i][nt][3]);
            }
    } else {
        u32* O = (which==0 ? g_qp : g_kp) + rowbase*64;
        float sc = (which==0) ? 0.125f : 1.0f;
        #pragma unroll
        for (int i = 0; i < 2; i++)
            #pragma unroll
            for (int nt = 0; nt < 8; nt++){
                int ix = ((nt>>1)<<4) + tc*4 + 2*(nt&1);
                u32 hi, lo;
                packpair(c[i][nt][0]*sc, c[i][nt][1]*sc, hi, lo);
                *(u64*)(O + (size_t)(rb+16*i+grp)*64 + ix) = (u64)hi | ((u64)lo<<32);
                packpair(c[i][nt][2]*sc, c[i][nt][3]*sc, hi, lo);
                *(u64*)(O + (size_t)(rb+16*i+grp+8)*64 + ix) = (u64)hi | ((u64)lo<<32);
            }
    }
}

// ===== attention: 256 thr (8 warps), q-tile 256 (R=2), k64, P hi-only =====
#define AT_BUF (64*68*2)
#define AT_SMEM ((AT_BUF*2 + 256*36)*4)    // 106496 B
__global__ void __launch_bounds__(256,2) attn_kernel(float* __restrict__ out_sha){
    extern __shared__ u32 smu[];
    u32* sP = smu + AT_BUF*2;
    int tid = threadIdx.x, w = tid>>5, lane = tid&31, grp = lane>>2, tc = lane&3, rb = w*32;
    int qt = blockIdx.x, m = blockIdx.y, b = blockIdx.z, bm = b*MN + m;
    const u32* Qg = g_qp + ((size_t)bm*TN + (size_t)qt*256)*64;
    const u32* Kg = g_kp + (size_t)bm*TN*64;
    const u32* Vg = g_vp + (size_t)bm*64*2048;
    u32 sbase = s2u(smu);

    {
        u32 bK = sbase, bV = sbase + 64*68*4;
        #pragma unroll
        for (int j = 0; j < 4; j++){ int u = j*256+tid, row = u>>4, q = (u&15)*4;
            cpa16(bK + (row*68 + q)*4, Kg + (size_t)row*64 + q);
            cpa16(bV + (row*68 + q)*4, Vg + (size_t)row*2048 + q);
        }
        CPA_COMMIT();
    }

    u32 qh[2][4][4], ql[2][4][4];
    #pragma unroll
    for (int i = 0; i < 2; i++)
        #pragma unroll
        for (int kc = 0; kc < 4; kc++){
            uint4 r0 = *(const uint4*)(Qg + (size_t)(rb+16*i+grp)*64 + kc*16 + tc*4);
            uint4 r1 = *(const uint4*)(Qg + (size_t)(rb+16*i+grp+8)*64 + kc*16 + tc*4);
            qh[i][kc][0]=r0.x; qh[i][kc][1]=r1.x; qh[i][kc][2]=r0.z; qh[i][kc][3]=r1.z;
            ql[i][kc][0]=r0.y; ql[i][kc][1]=r1.y; ql[i][kc][2]=r0.w; ql[i][kc][3]=r1.w;
        }

    float o[2][8][4] = {};
    float lsum[2][2] = {}, tsum[2][2] = {};

    for (int kt = 0; kt < TN/64; kt++){
        __syncthreads();
        if (kt+1 < TN/64){
            u32 bK = sbase + ((kt+1)&1)*AT_BUF*4, bV = bK + 64*68*4;
            #pragma unroll
            for (int j = 0; j < 4; j++){ int u = j*256+tid, row = u>>4, q = (u&15)*4;
                cpa16(bK + (row*68 + q)*4, Kg + (size_t)((kt+1)*64+row)*64 + q);
                cpa16(bV + (row*68 + q)*4, Vg + (size_t)row*2048 + (kt+1)*64 + q);
            }
            CPA_COMMIT();
            CPA_WAIT1();
        } else {
            CPA_WAIT0();
        }
        __syncthreads();
        u32* sK = smu + (kt&1)*AT_BUF;
        u32* sV = sK + 64*68;

        #pragma unroll
        for (int nt = 0; nt < 8; nt++){
            float s0[4] = {}, s1[4] = {};
            #pragma unroll
            for (int kc = 0; kc < 4; kc++){
                uint4 bb = *(uint4*)(sK + (nt*8+grp)*68 + kc*16 + tc*4);
                mma16(s0, qh[0][kc][0], qh[0][kc][1], qh[0][kc][2], qh[0][kc][3], bb.x, bb.z);
                mma16(s0, qh[0][kc][0], qh[0][kc][1], qh[0][kc][2], qh[0][kc][3], bb.y, bb.w);
                mma16(s0, ql[0][kc][0], ql[0][kc][1], ql[0][kc][2], ql[0][kc][3], bb.x, bb.z);
                mma16(s1, qh[1][kc][0], qh[1][kc][1], qh[1][kc][2], qh[1][kc][3], bb.x, bb.z);
                mma16(s1, qh[1][kc][0], qh[1][kc][1], qh[1][kc][2], qh[1][kc][3], bb.y, bb.w);
                mma16(s1, ql[1][kc][0], ql[1][kc][1], ql[1][kc][2], ql[1][kc][3], bb.x, bb.z);
            }
            int ix = ((nt>>1)<<3) + 2*tc + (nt&1);
            #pragma unroll
            for (int i = 0; i < 2; i++){
                float* s = i ? s1 : s0;
                float p0 = __expf(s[0]), p1 = __expf(s[1]);
                float p2 = __expf(s[2]), p3 = __expf(s[3]);
                lsum[i][0] += p0 + p1; tsum[i][0] += p0*s[0] + p1*s[1];
                lsum[i][1] += p2 + p3; tsum[i][1] += p2*s[2] + p3*s[3];
                sP[(rb+16*i+grp)*36 + ix]   = packhi(p0, p1);
                sP[(rb+16*i+grp+8)*36 + ix] = packhi(p2, p3);
            }
        }
        __syncwarp();

        #pragma unroll
        for (int kc = 0; kc < 4; kc++){
            uint2 P0[2], P1[2];
            #pragma unroll
            for (int i = 0; i < 2; i++){
                P0[i] = *(uint2*)(sP + (rb+16*i+grp)*36 + kc*8 + 2*tc);
                P1[i] = *(uint2*)(sP + (rb+16*i+grp+8)*36 + kc*8 + 2*tc);
            }
            #pragma unroll
            for (int nt = 0; nt < 8; nt++){
                uint4 bb = *(uint4*)(sV + (nt*8+grp)*68 + kc*16 + tc*4);
                #pragma unroll
                for (int i = 0; i < 2; i++){
                    mma16(o[i][nt], P0[i].x, P1[i].x, P0[i].y, P1[i].y, bb.x, bb.z);
                    mma16(o[i][nt], P0[i].x, P1[i].x, P0[i].y, P1[i].y, bb.y, bb.w);
                }
            }
        }
        __syncwarp();
    }

    #pragma unroll
    for (int i = 0; i < 2; i++)
        #pragma unroll
        for (int h = 0; h < 2; h++){
            lsum[i][h] += __shfl_xor_sync(0xffffffffu, lsum[i][h], 1);
            lsum[i][h] += __shfl_xor_sync(0xffffffffu, lsum[i][h], 2);
            tsum[i][h] += __shfl_xor_sync(0xffffffffu, tsum[i][h], 1);
            tsum[i][h] += __shfl_xor_sync(0xffffffffu, tsum[i][h], 2);
        }
    #pragma unroll
    for (int i = 0; i < 2; i++){
        float inv0 = 1.f/lsum[i][0], inv1 = 1.f/lsum[i][1];
        size_t t0 = (size_t)qt*256 + rb + 16*i + grp;
        float* op0 = out_sha + (((size_t)b*TN + t0)*MN + m)*DN;
        float* op1 = out_sha + (((size_t)b*TN + t0 + 8)*MN + m)*DN;
        #pragma unroll
        for (int nt = 0; nt < 8; nt++){
            int col = nt*8 + 2*tc;
            *(float2*)(op0 + col) = make_float2(o[i][nt][0]*inv0, o[i][nt][1]*inv0);
            *(float2*)(op1 + col) = make_float2(o[i][nt][2]*inv1, o[i][nt][3]*inv1);
        }
    }
    float e = 0.f;
    #pragma unroll
    for (int i = 0; i < 2; i++)
        #pragma unroll
        for (int h = 0; h < 2; h++)
            e += logf(lsum[i][h]) - tsum[i][h]/lsum[i][h];
    #pragma unroll
    for (int off = 16; off; off >>= 1) e += __shfl_xor_sync(0xffffffffu, e, off);
    if (lane == 0) atomicAdd(&g_ent[bm], (double)(e * 0.25f));
}

// ===== gating =====
__global__ void gate_kernel(const float* __restrict__ gates, float* __restrict__ out){
    __shared__ int cnt;
    int tid = threadIdx.x;
    if (tid == 0) cnt = 0;
    __syncthreads();
    int m = tid & 15;
    float aff = -(float)(g_ent[tid] * (1.0 / (double)TN));
    float s = aff;
    #pragma unroll
    for (int off = 8; off; off >>= 1) s += __shfl_xor_sync(0xffffffffu, s, off);
    float mu = s * (1.f/16.f);
    float d = aff - mu, v = d*d;
    #pragma unroll
    for (int off = 8; off; off >>= 1) v += __shfl_xor_sync(0xffffffffu, v, off);
    float sd = sqrtf(v * (1.f/15.f));
    float norm = d / (sd + 1e-9f);
    float logit = norm - 1.f/(1.f + expf(-gates[m]));
    float hard = (logit > 0.f) ? 1.f : 0.f;
    float nact = hard;
    #pragma unroll
    for (int off = 8; off; off >>= 1) nact += __shfl_xor_sync(0xffffffffu, nact, off);
    bool inactive = (nact == 0.f);
    float v1 = norm; int i1 = m;
    #pragma unroll
    for (int off = 8; off; off >>= 1){
        float ov = __shfl_xor_sync(0xffffffffu, v1, off);
        int oi = __shfl_xor_sync(0xffffffffu, i1, off);
        if (ov > v1 || (ov == v1 && oi < i1)){ v1 = ov; i1 = oi; }
    }
    float v2 = (m == i1) ? -INFINITY : norm; int i2 = m;
    #pragma unroll
    for (int off = 8; off; off >>= 1){
        float ov = __shfl_xor_sync(0xffffffffu, v2, off);
        int oi = __shfl_xor_sync(0xffffffffu, i2, off);
        if (ov > v2 || (ov == v2 && oi < i2)){ v2 = ov; i2 = oi; }
    }
    float mask = hard;
    if (inactive && (m == i1 || m == i2)) mask = 1.f;
    float na = mask;
    #pragma unroll
    for (int off = 8; off; off >>= 1) na += __shfl_xor_sync(0xffffffffu, na, off);
    float nm = mask / fmaxf(na, 1.f);
    out[OFF_LOGIT + tid] = logit;
    out[OFF_MASK + tid] = mask;
    g_nmask[tid] = nm;
    if (m == 0 && inactive) atomicAdd(&cnt, 1);
    __syncthreads();
    if (tid == 0) out[OFF_FBC] = (float)cnt;
}

// ===== combine / oproj / final =====
__global__ void combine_kernel(const float* __restrict__ sha){
    __shared__ float snm[32];
    if (threadIdx.x < 32) snm[threadIdx.x] = g_nmask[threadIdx.x];
    __syncthreads();
    int idx4 = blockIdx.x*256 + threadIdx.x;
    int d4 = (idx4 & 15) << 2, t = (idx4 >> 4) & (TN-1), b = idx4 >> 15;
    const float* base = sha + ((size_t)(b*TN + t)*MN)*DN + d4;
    const float* w = snm + b*16;
    float4 acc = make_float4(0.f,0.f,0.f,0.f);
    #pragma unroll
    for (int mm = 0; mm < MN; mm++){
        float4 v = *(const float4*)(base + mm*DN);
        float wm = w[mm];
        acc.x = fmaf(v.x,wm,acc.x); acc.y = fmaf(v.y,wm,acc.y);
        acc.z = fmaf(v.z,wm,acc.z); acc.w = fmaf(v.w,wm,acc.w);
    }
    *(float4*)(g_comb + (size_t)idx4*4) = acc;
}
__global__ void oproj_kernel(const float* __restrict__ ow){
    __shared__ float snm[32];
    if (threadIdx.x < 32) snm[threadIdx.x] = g_nmask[threadIdx.x];
    __syncthreads();
    int idx4 = blockIdx.x*256 + threadIdx.x;
    int h4 = (idx4 & 255) << 2, dd = (idx4 >> 8) & 63, b = idx4 >> 14;
    float4 acc = make_float4(0.f,0.f,0.f,0.f);
    #pragma unroll
    for (int mm = 0; mm < MN; mm++){
        float4 v = *(const float4*)(ow + ((size_t)mm*DN + dd)*HN + h4);
        float wm = snm[b*16 + mm];
        acc.x = fmaf(v.x,wm,acc.x); acc.y = fmaf(v.y,wm,acc.y);
        acc.z = fmaf(v.z,wm,acc.z); acc.w = fmaf(v.w,wm,acc.w);
    }
    *(float4*)(g_oproj + (size_t)idx4*4) = acc;
}
__global__ void final_kernel(float* __restrict__ out){
    __shared__ float smem[16*68 + 16*64];
    float* sAt = smem;
    float* sB = smem + 16*68;
    int tid = threadIdx.x;
    int r0 = (tid >> 4) << 2, c0 = (tid & 15) << 2;
    int arow = tid >> 2, ak = (tid & 3) << 2;
    int wkr = tid >> 4, wn = (tid & 15) << 2;
    int ht = blockIdx.x, qt = blockIdx.y, b = blockIdx.z;
    const float* A = g_comb + (size_t)b*TN*DN + (size_t)qt*64*DN;
    const float* W = g_oproj + (size_t)b*DN*HN + ht*64;
    float* C = out + (size_t)b*TN*HN + (size_t)qt*64*HN + ht*64;
    u64 acc2[4][2] = {};
    for (int k0 = 0; k0 < DN; k0 += 16){
        __syncthreads();
        float4 av = *(const float4*)(A + (size_t)arow*DN + k0 + ak);
        sAt[(ak+0)*68+arow]=av.x; sAt[(ak+1)*68+arow]=av.y;
        sAt[(ak+2)*68+arow]=av.z; sAt[(ak+3)*68+arow]=av.w;
        *(float4*)(sB + wkr*64 + wn) = *(const float4*)(W + (size_t)(k0+wkr)*HN + wn);
        __syncthreads();
        #pragma unroll
        for (int kk = 0; kk < 16; kk++){
            float4 a4 = *(const float4*)(sAt + kk*68 + r0);
            ulonglong2 bu = *(const ulonglong2*)(sB + kk*64 + c0);
            u64 a0 = pk2f(a4.x,a4.x), a1 = pk2f(a4.y,a4.y);
            u64 a2 = pk2f(a4.z,a4.z), a3 = pk2f(a4.w,a4.w);
            ffma2(acc2[0][0],a0,bu.x); ffma2(acc2[0][1],a0,bu.y);
            ffma2(acc2[1][0],a1,bu.x); ffma2(acc2[1][1],a1,bu.y);
            ffma2(acc2[2][0],a2,bu.x); ffma2(acc2[2][1],a2,bu.y);
            ffma2(acc2[3][0],a3,bu.x); ffma2(acc2[3][1],a3,bu.y);
        }
    }
    #pragma unroll
    for (int i = 0; i < 4; i++){
        float4 o;
        upk2f(o.x,o.y,acc2[i][0]); upk2f(o.z,o.w,acc2[i][1]);
        *(float4*)(C + (size_t)(r0+i)*HN + c0) = o;
    }
}

extern "C" void kernel_launch(void* const* d_in, const int* in_sizes, int n_in,
                              void* d_out, int out_size)
{
    const float* hs    = (const float*)d_in[0];
    const float* wq    = (const float*)d_in[1];
    const float* wk    = (const float*)d_in[2];
    const float* wv    = (const float*)d_in[3];
    const float* ow    = (const float*)d_in[4];
    const float* gates = (const float*)d_in[5];
    float* out = (float*)d_out;

    cudaFuncSetAttribute(proj_kernel, cudaFuncAttributeMaxDynamicSharedMemorySize, PJ_SMEM);
    cudaFuncSetAttribute(attn_kernel, cudaFuncAttributeMaxDynamicSharedMemorySize, AT_SMEM);

    init_kernel<<<1, 32>>>();
    split_hs_kernel<<<BN*TN, 256>>>(hs);
    split_w_kernel<<<dim3(512, 3), 256>>>(wq, wk, wv);
    proj_kernel<<<dim3(8, 16, 6), 256, PJ_SMEM>>>();
    repack_v_kernel<<<dim3(64, 32), 256>>>();
    attn_kernel<<<dim3(8, 16, 2), 256, AT_SMEM>>>(out + OFF_SHA);
    gate_kernel<<<1, 32>>>(gates, out);
    combine_kernel<<<256, 256>>>(out + OFF_SHA);
    oproj_kernel<<<128, 256>>>(ow);
    final_kernel<<<dim3(16, 32, 2), 256>>>(out);
}

// round 14
// speedup vs baseline: 1.1401x; 1.1401x over previous
#include <cuda_runtime.h>
#include <cuda_fp16.h>
#include <math.h>

#define BN 2
#define TN 2048
#define HN 1024
#define DN 64
#define MN 16
#define QKV_ELEMS (BN*MN*TN*DN)
typedef unsigned long long u64;
typedef unsigned int u32;

__device__ __forceinline__ void mma16(float* d, u32 a0, u32 a1, u32 a2, u32 a3, u32 b0, u32 b1){
    asm volatile("mma.sync.aligned.m16n8k16.row.col.f32.f16.f16.f32 "
        "{%0,%1,%2,%3},{%4,%5,%6,%7},{%8,%9},{%0,%1,%2,%3};"
        : "+f"(d[0]),"+f"(d[1]),"+f"(d[2]),"+f"(d[3])
        : "r"(a0),"r"(a1),"r"(a2),"r"(a3),"r"(b0),"r"(b1));
}
__device__ __forceinline__ void packpair(float v0, float v1, u32& hi, u32& lo){
    __half h0 = __float2half_rn(v0), h1 = __float2half_rn(v1);
    __half2 H = __halves2half2(h0, h1);
    __half2 L = __halves2half2(__float2half_rn(v0 - __half2float(h0)),
                               __float2half_rn(v1 - __half2float(h1)));
    hi = *(u32*)&H; lo = *(u32*)&L;
}
__device__ __forceinline__ u32 packhi(float v0, float v1){
    __half2 H = __halves2half2(__float2half_rn(v0), __float2half_rn(v1));
    return *(u32*)&H;
}
__device__ __forceinline__ int pidx(int p){
    return ((p>>3)<<4) + ((p&3)<<2) + (((p>>2)&1)<<1);
}
__device__ __forceinline__ u64 pk2f(float lo, float hi){
    u64 r; asm("mov.b64 %0, {%1,%2};" : "=l"(r) : "f"(lo), "f"(hi)); return r;
}
__device__ __forceinline__ void upk2f(float& lo, float& hi, u64 v){
    asm("mov.b64 {%0,%1}, %2;" : "=f"(lo), "=f"(hi) : "l"(v));
}
__device__ __forceinline__ void ffma2(u64& d, u64 a, u64 b){
    asm("fma.rn.f32x2 %0, %1, %2, %0;" : "+l"(d) : "l"(a), "l"(b));
}
__device__ __forceinline__ u32 s2u(const void* p){
    u32 a; asm("{ .reg .u64 t; cvta.to.shared.u64 t, %1; cvt.u32.u64 %0, t; }":"=r"(a):"l"(p)); return a;
}
__device__ __forceinline__ void cpa16(u32 dst, const void* src){
    asm volatile("cp.async.cg.shared.global [%0], [%1], 16;" :: "r"(dst), "l"(src) : "memory");
}
#define CPA_COMMIT() asm volatile("cp.async.commit_group;" ::: "memory")
#define CPA_WAIT1()  asm volatile("cp.async.wait_group 1;" ::: "memory")
#define CPA_WAIT0()  asm volatile("cp.async.wait_group 0;" ::: "memory")

__device__ u32   g_hsp[BN*TN*1024];
__device__ u32   g_wp[3*MN*64*1024];
__device__ u32   g_qp[BN*MN*TN*64];
__device__ u32   g_kp[BN*MN*TN*64];
__device__ float g_v[QKV_ELEMS];
__device__ u32   g_vp[BN*MN*64*2048];
__device__ double g_ent[BN*MN];
__device__ float g_nmask[BN*MN];
__device__ float g_comb[BN*TN*DN];
__device__ float g_oproj[BN*DN*HN];

#define OFF_SHA   (BN*TN*HN)
#define OFF_LOGIT (OFF_SHA + BN*TN*MN*DN)
#define OFF_MASK  (OFF_LOGIT + BN*MN)
#define OFF_FBC   (OFF_MASK + BN*MN)

__global__ void init_kernel(){ g_ent[threadIdx.x] = 0.0; }

__global__ void split_hs_kernel(const float* __restrict__ hs){
    int row = blockIdx.x, t = threadIdx.x;
    float4 v = *(const float4*)(hs + (size_t)row*1024 + t*4);
    u32 hi, lo;
    u32* O = g_hsp + (size_t)row*1024;
    packpair(v.x, v.y, hi, lo); *(u64*)(O + pidx(2*t))   = (u64)hi | ((u64)lo<<32);
    packpair(v.z, v.w, hi, lo); *(u64*)(O + pidx(2*t+1)) = (u64)hi | ((u64)lo<<32);
}
__global__ void split_w_kernel(const float* __restrict__ wq, const float* __restrict__ wk,
                               const float* __restrict__ wv){
    int which = blockIdx.y;
    const float* W = which==0 ? wq : which==1 ? wk : wv;
    int flat = blockIdx.x*256 + threadIdx.x;
    int mx = flat >> 13, r = flat & 8191, p = r >> 4, d4 = (r & 15) * 4;
    const float* Wm = W + (size_t)mx*HN*DN;
    float4 va = *(const float4*)(Wm + (size_t)(2*p)*DN + d4);
    float4 vb = *(const float4*)(Wm + (size_t)(2*p+1)*DN + d4);
    u32* O = g_wp + (size_t)(which*MN + mx)*64*1024;
    float a[4] = {va.x, va.y, va.z, va.w}, bq[4] = {vb.x, vb.y, vb.z, vb.w};
    int ix = pidx(p);
    #pragma unroll
    for (int e = 0; e < 4; e++){
        u32 hi, lo; packpair(a[e], bq[e], hi, lo);
        *(u64*)(O + (size_t)(d4+e)*1024 + ix) = (u64)hi | ((u64)lo<<32);
    }
}
__global__ void repack_v_kernel(){
    int flat = blockIdx.x*256 + threadIdx.x;
    int bm = blockIdx.y;
    int p = flat >> 4, d4 = (flat & 15) * 4;
    const float* V = g_v + (size_t)bm*TN*64;
    float4 va = *(const float4*)(V + (size_t)(2*p)*64 + d4);
    float4 vb = *(const float4*)(V + (size_t)(2*p+1)*64 + d4);
    u32* O = g_vp + (size_t)bm*64*2048;
    float a[4] = {va.x, va.y, va.z, va.w}, bq[4] = {vb.x, vb.y, vb.z, vb.w};
    int ix = pidx(p);
    #pragma unroll
    for (int e = 0; e < 4; e++){
        u32 hi, lo; packpair(a[e], bq[e], hi, lo);
        *(u64*)(O + (size_t)(d4+e)*2048 + ix) = (u64)hi | ((u64)lo<<32);
    }
}

// ===== proj: 128 thr, R=2, fp16x3 k16 mma, 32-k stages, cp.async ring =====
#define PJ_STG (128*36 + 64*36)
#define PJ_SMEM (PJ_STG*2*4)
__global__ void __launch_bounds__(128,4) proj_kernel(){
    extern __shared__ u32 smu[];
    int tid = threadIdx.x, w = tid>>5, lane = tid&31, grp = lane>>2, tc = lane&3, rb = w*32;
    int qt = blockIdx.x, mx = blockIdx.y, b = blockIdx.z/3, which = blockIdx.z%3;
    const u32* Ag = g_hsp + (size_t)(b*TN + qt*128)*1024;
    const u32* Wg = g_wp + (size_t)(which*MN + mx)*64*1024;
    u32 sbase = s2u(smu);

    {
        u32 bA = sbase, bW = sbase + 128*36*4;
        #pragma unroll
        for (int j = 0; j < 8; j++){ int u = j*128+tid, row = u>>3, q = (u&7)*4;
            cpa16(bA + (row*36 + q)*4, Ag + (size_t)row*1024 + q); }
        #pragma unroll
        for (int j = 0; j < 4; j++){ int u = j*128+tid, row = u>>3, q = (u&7)*4;
            cpa16(bW + (row*36 + q)*4, Wg + (size_t)row*1024 + q); }
        CPA_COMMIT();
    }

    float c[2][8][4] = {};
    for (int st = 0; st < 32; st++){
        __syncthreads();
        if (st+1 < 32){
            u32 bA = sbase + ((st+1)&1)*PJ_STG*4, bW = bA + 128*36*4;
            int off = (st+1)*32;
            #pragma unroll
            for (int j = 0; j < 8; j++){ int u = j*128+tid, row = u>>3, q = (u&7)*4;
                cpa16(bA + (row*36 + q)*4, Ag + (size_t)row*1024 + off + q); }
            #pragma unroll
            for (int j = 0; j < 4; j++){ int u = j*128+tid, row = u>>3, q = (u&7)*4;
                cpa16(bW + (row*36 + q)*4, Wg + (size_t)row*1024 + off + q); }
            CPA_COMMIT();
            CPA_WAIT1();
        } else {
            CPA_WAIT0();
        }
        __syncthreads();
        u32* sA = smu + (st&1)*PJ_STG;
        u32* sW = sA + 128*36;
        #pragma unroll
        for (int kc = 0; kc < 2; kc++){
            uint4 A0[2], A1[2];
            #pragma unroll
            for (int i = 0; i < 2; i++){
                A0[i] = *(uint4*)(sA + (rb+16*i+grp)*36 + kc*16 + tc*4);
                A1[i] = *(uint4*)(sA + (rb+16*i+grp+8)*36 + kc*16 + tc*4);
            }
            #pragma unroll
            for (int nt = 0; nt < 8; nt++){
                uint4 bb = *(uint4*)(sW + (nt*8+grp)*36 + kc*16 + tc*4);
                #pragma unroll
                for (int i = 0; i < 2; i++){
                    mma16(c[i][nt], A0[i].x, A1[i].x, A0[i].z, A1[i].z, bb.x, bb.z);
                    mma16(c[i][nt], A0[i].x, A1[i].x, A0[i].z, A1[i].z, bb.y, bb.w);
                    mma16(c[i][nt], A0[i].y, A1[i].y, A0[i].w, A1[i].w, bb.x, bb.z);
                }
            }
        }
    }
    size_t rowbase = (size_t)(b*MN + mx)*TN + (size_t)qt*128;
    if (which == 2){
        #pragma unroll
        for (int i = 0; i < 2; i++)
            #pragma unroll
            for (int nt = 0; nt < 8; nt++){
                int col = nt*8 + 2*tc;
                *(float2*)(g_v + (rowbase + rb+16*i+grp)*64 + col)   = make_float2(c[i][nt][0], c[i][nt][1]);
                *(float2*)(g_v + (rowbase + rb+16*i+grp+8)*64 + col) = make_float2(c[i][nt][2], c[i][nt][3]);
            }
    } else {
        u32* O = (which==0 ? g_qp : g_kp) + rowbase*64;
        float sc = (which==0) ? 0.125f : 1.0f;
        #pragma unroll
        for (int i = 0; i < 2; i++)
            #pragma unroll
            for (int nt = 0; nt < 8; nt++){
                int ix = ((nt>>1)<<4) + tc*4 + 2*(nt&1);
                u32 hi, lo;
                packpair(c[i][nt][0]*sc, c[i][nt][1]*sc, hi, lo);
                *(u64*)(O + (size_t)(rb+16*i+grp)*64 + ix) = (u64)hi | ((u64)lo<<32);
                packpair(c[i][nt][2]*sc, c[i][nt][3]*sc, hi, lo);
                *(u64*)(O + (size_t)(rb+16*i+grp+8)*64 + ix) = (u64)hi | ((u64)lo<<32);
            }
    }
}

// ===== attention: q128 (R=2), k64, no max-sub, QK 2-term, P hi-only =====
#define AT_BUF (64*68*2)
#define AT_SMEM ((AT_BUF*2 + 128*36)*4)
__global__ void __launch_bounds__(128,2) attn_kernel(float* __restrict__ out_sha){
    extern __shared__ u32 smu[];
    u32* sP = smu + AT_BUF*2;
    int tid = threadIdx.x, w = tid>>5, lane = tid&31, grp = lane>>2, tc = lane&3, rb = w*32;
    int qt = blockIdx.x, m = blockIdx.y, b = blockIdx.z, bm = b*MN + m;
    const u32* Qg = g_qp + ((size_t)bm*TN + (size_t)qt*128)*64;
    const u32* Kg = g_kp + (size_t)bm*TN*64;
    const u32* Vg = g_vp + (size_t)bm*64*2048;
    u32 sbase = s2u(smu);

    {
        u32 bK = sbase, bV = sbase + 64*68*4;
        #pragma unroll
        for (int j = 0; j < 8; j++){ int u = j*128+tid, row = u>>4, q = (u&15)*4;
            cpa16(bK + (row*68 + q)*4, Kg + (size_t)row*64 + q);
            cpa16(bV + (row*68 + q)*4, Vg + (size_t)row*2048 + q);
        }
        CPA_COMMIT();
    }

    u32 qh[2][4][4];
    #pragma unroll
    for (int i = 0; i < 2; i++)
        #pragma unroll
        for (int kc = 0; kc < 4; kc++){
            uint4 r0 = *(const uint4*)(Qg + (size_t)(rb+16*i+grp)*64 + kc*16 + tc*4);
            uint4 r1 = *(const uint4*)(Qg + (size_t)(rb+16*i+grp+8)*64 + kc*16 + tc*4);
            qh[i][kc][0]=r0.x; qh[i][kc][1]=r1.x; qh[i][kc][2]=r0.z; qh[i][kc][3]=r1.z;
        }

    float o[2][8][4] = {};
    float lsum[2][2] = {}, tsum[2][2] = {};

    for (int kt = 0; kt < TN/64; kt++){
        __syncthreads();
        if (kt+1 < TN/64){
            u32 bK = sbase + ((kt+1)&1)*AT_BUF*4, bV = bK + 64*68*4;
            #pragma unroll
            for (int j = 0; j < 8; j++){ int u = j*128+tid, row = u>>4, q = (u&15)*4;
                cpa16(bK + (row*68 + q)*4, Kg + (size_t)((kt+1)*64+row)*64 + q);
                cpa16(bV + (row*68 + q)*4, Vg + (size_t)row*2048 + (kt+1)*64 + q);
            }
            CPA_COMMIT();
            CPA_WAIT1();
        } else {
            CPA_WAIT0();
        }
        __syncthreads();
        u32* sK = smu + (kt&1)*AT_BUF;
        u32* sV = sK + 64*68;

        #pragma unroll
        for (int nt = 0; nt < 8; nt++){
            float s0[4] = {}, s1[4] = {};
            #pragma unroll
            for (int kc = 0; kc < 4; kc++){
                uint4 bb = *(uint4*)(sK + (nt*8+grp)*68 + kc*16 + tc*4);
                mma16(s0, qh[0][kc][0], qh[0][kc][1], qh[0][kc][2], qh[0][kc][3], bb.x, bb.z);
                mma16(s0, qh[0][kc][0], qh[0][kc][1], qh[0][kc][2], qh[0][kc][3], bb.y, bb.w);
                mma16(s1, qh[1][kc][0], qh[1][kc][1], qh[1][kc][2], qh[1][kc][3], bb.x, bb.z);
                mma16(s1, qh[1][kc][0], qh[1][kc][1], qh[1][kc][2], qh[1][kc][3], bb.y, bb.w);
            }
            int ix = ((nt>>1)<<3) + 2*tc + (nt&1);
            #pragma unroll
            for (int i = 0; i < 2; i++){
                float* s = i ? s1 : s0;
                float p0 = __expf(s[0]), p1 = __expf(s[1]);
                float p2 = __expf(s[2]), p3 = __expf(s[3]);
                lsum[i][0] += p0 + p1; tsum[i][0] += p0*s[0] + p1*s[1];
                lsum[i][1] += p2 + p3; tsum[i][1] += p2*s[2] + p3*s[3];
                sP[(rb+16*i+grp)*36 + ix]   = packhi(p0, p1);
                sP[(rb+16*i+grp+8)*36 + ix] = packhi(p2, p3);
            }
        }
        __syncwarp();

        #pragma unroll
        for (int kc = 0; kc < 4; kc++){
            uint2 P0[2], P1[2];
            #pragma unroll
            for (int i = 0; i < 2; i++){
                P0[i] = *(uint2*)(sP + (rb+16*i+grp)*36 + kc*8 + 2*tc);
                P1[i] = *(uint2*)(sP + (rb+16*i+grp+8)*36 + kc*8 + 2*tc);
            }
            #pragma unroll
            for (int nt = 0; nt < 8; nt++){
                uint4 bb = *(uint4*)(sV + (nt*8+grp)*68 + kc*16 + tc*4);
                #pragma unroll
                for (int i = 0; i < 2; i++){
                    mma16(o[i][nt], P0[i].x, P1[i].x, P0[i].y, P1[i].y, bb.x, bb.z);
                    mma16(o[i][nt], P0[i].x, P1[i].x, P0[i].y, P1[i].y, bb.y, bb.w);
                }
            }
        }
        __syncwarp();
    }

    #pragma unroll
    for (int i = 0; i < 2; i++)
        #pragma unroll
        for (int h = 0; h < 2; h++){
            lsum[i][h] += __shfl_xor_sync(0xffffffffu, lsum[i][h], 1);
            lsum[i][h] += __shfl_xor_sync(0xffffffffu, lsum[i][h], 2);
            tsum[i][h] += __shfl_xor_sync(0xffffffffu, tsum[i][h], 1);
            tsum[i][h] += __shfl_xor_sync(0xffffffffu, tsum[i][h], 2);
        }
    #pragma unroll
    for (int i = 0; i < 2; i++){
        float inv0 = 1.f/lsum[i][0], inv1 = 1.f/lsum[i][1];
        size_t t0 = (size_t)qt*128 + rb + 16*i + grp;
        float* op0 = out_sha + (((size_t)b*TN + t0)*MN + m)*DN;
        float* op1 = out_sha + (((size_t)b*TN + t0 + 8)*MN + m)*DN;
        #pragma unroll
        for (int nt = 0; nt < 8; nt++){
            int col = nt*8 + 2*tc;
            *(float2*)(op0 + col) = make_float2(o[i][nt][0]*inv0, o[i][nt][1]*inv0);
            *(float2*)(op1 + col) = make_float2(o[i][nt][2]*inv1, o[i][nt][3]*inv1);
        }
    }
    float e = 0.f;
    #pragma unroll
    for (int i = 0; i < 2; i++)
        #pragma unroll
        for (int h = 0; h < 2; h++)
            e += logf(lsum[i][h]) - tsum[i][h]/lsum[i][h];
    #pragma unroll
    for (int off = 16; off; off >>= 1) e += __shfl_xor_sync(0xffffffffu, e, off);
    if (lane == 0) atomicAdd(&g_ent[bm], (double)(e * 0.25f));
}

// ===== gating =====
__global__ void gate_kernel(const float* __restrict__ gates, float* __restrict__ out){
    __shared__ int cnt;
    int tid = threadIdx.x;
    if (tid == 0) cnt = 0;
    __syncthreads();
    int m = tid & 15;
    float aff = -(float)(g_ent[tid] * (1.0 / (double)TN));
    float s = aff;
    #pragma unroll
    for (int off = 8; off; off >>= 1) s += __shfl_xor_sync(0xffffffffu, s, off);
    float mu = s * (1.f/16.f);
    float d = aff - mu, v = d*d;
    #pragma unroll
    for (int off = 8; off; off >>= 1) v += __shfl_xor_sync(0xffffffffu, v, off);
    float sd = sqrtf(v * (1.f/15.f));
    float norm = d / (sd + 1e-9f);
    float logit = norm - 1.f/(1.f + expf(-gates[m]));
    float hard = (logit > 0.f) ? 1.f : 0.f;
    float nact = hard;
    #pragma unroll
    for (int off = 8; off; off >>= 1) nact += __shfl_xor_sync(0xffffffffu, nact, off);
    bool inactive = (nact == 0.f);
    float v1 = norm; int i1 = m;
    #pragma unroll
    for (int off = 8; off; off >>= 1){
        float ov = __shfl_xor_sync(0xffffffffu, v1, off);
        int oi = __shfl_xor_sync(0xffffffffu, i1, off);
        if (ov > v1 || (ov == v1 && oi < i1)){ v1 = ov; i1 = oi; }
    }
    float v2 = (m == i1) ? -INFINITY : norm; int i2 = m;
    #pragma unroll
    for (int off = 8; off; off >>= 1){
        float ov = __shfl_xor_sync(0xffffffffu, v2, off);
        int oi = __shfl_xor_sync(0xffffffffu, i2, off);
        if (ov > v2 || (ov == v2 && oi < i2)){ v2 = ov; i2 = oi; }
    }
    float mask = hard;
    if (inactive && (m == i1 || m == i2)) mask = 1.f;
    float na = mask;
    #pragma unroll
    for (int off = 8; off; off >>= 1) na += __shfl_xor_sync(0xffffffffu, na, off);
    float nm = mask / fmaxf(na, 1.f);
    out[OFF_LOGIT + tid] = logit;
    out[OFF_MASK + tid] = mask;
    g_nmask[tid] = nm;
    if (m == 0 && inactive) atomicAdd(&cnt, 1);
    __syncthreads();
    if (tid == 0) out[OFF_FBC] = (float)cnt;
}

// ===== combine / oproj / final =====
__global__ void combine_kernel(const float* __restrict__ sha){
    __shared__ float snm[32];
    if (threadIdx.x < 32) snm[threadIdx.x] = g_nmask[threadIdx.x];
    __syncthreads();
    int idx4 = blockIdx.x*256 + threadIdx.x;
    int d4 = (idx4 & 15) << 2, t = (idx4 >> 4) & (TN-1), b = idx4 >> 15;
    const float* base = sha + ((size_t)(b*TN + t)*MN)*DN + d4;
    const float* w = snm + b*16;
    float4 acc = make_float4(0.f,0.f,0.f,0.f);
    #pragma unroll
    for (int mm = 0; mm < MN; mm++){
        float4 v = *(const float4*)(base + mm*DN);
        float wm = w[mm];
        acc.x = fmaf(v.x,wm,acc.x); acc.y = fmaf(v.y,wm,acc.y);
        acc.z = fmaf(v.z,wm,acc.z); acc.w = fmaf(v.w,wm,acc.w);
    }
    *(float4*)(g_comb + (size_t)idx4*4) = acc;
}
__global__ void oproj_kernel(const float* __restrict__ ow){
    __shared__ float snm[32];
    if (threadIdx.x < 32) snm[threadIdx.x] = g_nmask[threadIdx.x];
    __syncthreads();
    int idx4 = blockIdx.x*256 + threadIdx.x;
    int h4 = (idx4 & 255) << 2, dd = (idx4 >> 8) & 63, b = idx4 >> 14;
    float4 acc = make_float4(0.f,0.f,0.f,0.f);
    #pragma unroll
    for (int mm = 0; mm < MN; mm++){
        float4 v = *(const float4*)(ow + ((size_t)mm*DN + dd)*HN + h4);
        float wm = snm[b*16 + mm];
        acc.x = fmaf(v.x,wm,acc.x); acc.y = fmaf(v.y,wm,acc.y);
        acc.z = fmaf(v.z,wm,acc.z); acc.w = fmaf(v.w,wm,acc.w);
    }
    *(float4*)(g_oproj + (size_t)idx4*4) = acc;
}
__global__ void final_kernel(float* __restrict__ out){
    __shared__ float smem[16*68 + 16*64];
    float* sAt = smem;
    float* sB = smem + 16*68;
    int tid = threadIdx.x;
    int r0 = (tid >> 4) << 2, c0 = (tid & 15) << 2;
    int arow = tid >> 2, ak = (tid & 3) << 2;
    int wkr = tid >> 4, wn = (tid & 15) << 2;
    int ht = blockIdx.x, qt = blockIdx.y, b = blockIdx.z;
    const float* A = g_comb + (size_t)b*TN*DN + (size_t)qt*64*DN;
    const float* W = g_oproj + (size_t)b*DN*HN + ht*64;
    float* C = out + (size_t)b*TN*HN + (size_t)qt*64*HN + ht*64;
    u64 acc2[4][2] = {};
    for (int k0 = 0; k0 < DN; k0 += 16){
        __syncthreads();
        float4 av = *(const float4*)(A + (size_t)arow*DN + k0 + ak);
        sAt[(ak+0)*68+arow]=av.x; sAt[(ak+1)*68+arow]=av.y;
        sAt[(ak+2)*68+arow]=av.z; sAt[(ak+3)*68+arow]=av.w;
        *(float4*)(sB + wkr*64 + wn) = *(const float4*)(W + (size_t)(k0+wkr)*HN + wn);
        __syncthreads();
        #pragma unroll
        for (int kk = 0; kk < 16; kk++){
            float4 a4 = *(const float4*)(sAt + kk*68 + r0);
            ulonglong2 bu = *(const ulonglong2*)(sB + kk*64 + c0);
            u64 a0 = pk2f(a4.x,a4.x), a1 = pk2f(a4.y,a4.y);
            u64 a2 = pk2f(a4.z,a4.z), a3 = pk2f(a4.w,a4.w);
            ffma2(acc2[0][0],a0,bu.x); ffma2(acc2[0][1],a0,bu.y);
            ffma2(acc2[1][0],a1,bu.x); ffma2(acc2[1][1],a1,bu.y);
            ffma2(acc2[2][0],a2,bu.x); ffma2(acc2[2][1],a2,bu.y);
            ffma2(acc2[3][0],a3,bu.x); ffma2(acc2[3][1],a3,bu.y);
        }
    }
    #pragma unroll
    for (int i = 0; i < 4; i++){
        float4 o;
        upk2f(o.x,o.y,acc2[i][0]); upk2f(o.z,o.w,acc2[i][1]);
        *(float4*)(C + (size_t)(r0+i)*HN + c0) = o;
    }
}

extern "C" void kernel_launch(void* const* d_in, const int* in_sizes, int n_in,
                              void* d_out, int out_size)
{
    const float* hs    = (const float*)d_in[0];
    const float* wq    = (const float*)d_in[1];
    const float* wk    = (const float*)d_in[2];
    const float* wv    = (const float*)d_in[3];
    const float* ow    = (const float*)d_in[4];
    const float* gates = (const float*)d_in[5];
    float* out = (float*)d_out;

    cudaFuncSetAttribute(proj_kernel, cudaFuncAttributeMaxDynamicSharedMemorySize, PJ_SMEM);
    cudaFuncSetAttribute(attn_kernel, cudaFuncAttributeMaxDynamicSharedMemorySize, AT_SMEM);

    init_kernel<<<1, 32>>>();
    split_hs_kernel<<<BN*TN, 256>>>(hs);
    split_w_kernel<<<dim3(512, 3), 256>>>(wq, wk, wv);
    proj_kernel<<<dim3(16, 16, 6), 128, PJ_SMEM>>>();
    repack_v_kernel<<<dim3(64, 32), 256>>>();
    attn_kernel<<<dim3(16, 16, 2), 128, AT_SMEM>>>(out + OFF_SHA);
    gate_kernel<<<1, 32>>>(gates, out);
    combine_kernel<<<256, 256>>>(out + OFF_SHA);
    oproj_kernel<<<128, 256>>>(ow);
    final_kernel<<<dim3(16, 32, 2), 256>>>(out);
}

// round 15
// speedup vs baseline: 1.3772x; 1.2080x over previous
#include <cuda_runtime.h>
#include <cuda_fp16.h>
#include <math.h>

#define BN 2
#define TN 2048
#define HN 1024
#define DN 64
#define MN 16
#define QKV_ELEMS (BN*MN*TN*DN)
typedef unsigned long long u64;
typedef unsigned int u32;

__device__ __forceinline__ void mma16(float* d, u32 a0, u32 a1, u32 a2, u32 a3, u32 b0, u32 b1){
    asm volatile("mma.sync.aligned.m16n8k16.row.col.f32.f16.f16.f32 "
        "{%0,%1,%2,%3},{%4,%5,%6,%7},{%8,%9},{%0,%1,%2,%3};"
        : "+f"(d[0]),"+f"(d[1]),"+f"(d[2]),"+f"(d[3])
        : "r"(a0),"r"(a1),"r"(a2),"r"(a3),"r"(b0),"r"(b1));
}
__device__ __forceinline__ void packpair(float v0, float v1, u32& hi, u32& lo){
    __half h0 = __float2half_rn(v0), h1 = __float2half_rn(v1);
    __half2 H = __halves2half2(h0, h1);
    __half2 L = __halves2half2(__float2half_rn(v0 - __half2float(h0)),
                               __float2half_rn(v1 - __half2float(h1)));
    hi = *(u32*)&H; lo = *(u32*)&L;
}
__device__ __forceinline__ u32 packhi(float v0, float v1){
    __half2 H = __halves2half2(__float2half_rn(v0), __float2half_rn(v1));
    return *(u32*)&H;
}
__device__ __forceinline__ int pidx(int p){
    return ((p>>3)<<4) + ((p&3)<<2) + (((p>>2)&1)<<1);
}
__device__ __forceinline__ int pidx_hi(int p){
    return ((p>>3)<<3) + ((p&3)<<1) + ((p>>2)&1);
}
__device__ __forceinline__ u64 pk2f(float lo, float hi){
    u64 r; asm("mov.b64 %0, {%1,%2};" : "=l"(r) : "f"(lo), "f"(hi)); return r;
}
__device__ __forceinline__ void upk2f(float& lo, float& hi, u64 v){
    asm("mov.b64 {%0,%1}, %2;" : "=f"(lo), "=f"(hi) : "l"(v));
}
__device__ __forceinline__ void ffma2(u64& d, u64 a, u64 b){
    asm("fma.rn.f32x2 %0, %1, %2, %0;" : "+l"(d) : "l"(a), "l"(b));
}
__device__ __forceinline__ u32 s2u(const void* p){
    u32 a; asm("{ .reg .u64 t; cvta.to.shared.u64 t, %1; cvt.u32.u64 %0, t; }":"=r"(a):"l"(p)); return a;
}
__device__ __forceinline__ void cpa16(u32 dst, const void* src){
    asm volatile("cp.async.cg.shared.global [%0], [%1], 16;" :: "r"(dst), "l"(src) : "memory");
}
#define CPA_COMMIT() asm volatile("cp.async.commit_group;" ::: "memory")
#define CPA_WAIT1()  asm volatile("cp.async.wait_group 1;" ::: "memory")
#define CPA_WAIT0()  asm volatile("cp.async.wait_group 0;" ::: "memory")

__device__ u32   g_hsp[BN*TN*1024];
__device__ u32   g_wp[3*MN*64*1024];
__device__ u32   g_qp[BN*MN*TN*64];
__device__ u32   g_kp[BN*MN*TN*64];
__device__ float g_v[QKV_ELEMS];
__device__ u32   g_vp[BN*MN*64*1024];     // V hi-only, [bm][d][1024]
__device__ double g_ent[BN*MN];
__device__ float g_nmask[BN*MN];
__device__ float g_comb[BN*TN*DN];
__device__ float g_oproj[BN*DN*HN];

#define OFF_SHA   (BN*TN*HN)
#define OFF_LOGIT (OFF_SHA + BN*TN*MN*DN)
#define OFF_MASK  (OFF_LOGIT + BN*MN)
#define OFF_FBC   (OFF_MASK + BN*MN)

__global__ void init_kernel(){ g_ent[threadIdx.x] = 0.0; }

__global__ void split_hs_kernel(const float* __restrict__ hs){
    int row = blockIdx.x, t = threadIdx.x;
    float4 v = *(const float4*)(hs + (size_t)row*1024 + t*4);
    u32 hi, lo;
    u32* O = g_hsp + (size_t)row*1024;
    packpair(v.x, v.y, hi, lo); *(u64*)(O + pidx(2*t))   = (u64)hi | ((u64)lo<<32);
    packpair(v.z, v.w, hi, lo); *(u64*)(O + pidx(2*t+1)) = (u64)hi | ((u64)lo<<32);
}
__global__ void split_w_kernel(const float* __restrict__ wq, const float* __restrict__ wk,
                               const float* __restrict__ wv){
    int which = blockIdx.y;
    const float* W = which==0 ? wq : which==1 ? wk : wv;
    int flat = blockIdx.x*256 + threadIdx.x;
    int mx = flat >> 13, r = flat & 8191, p = r >> 4, d4 = (r & 15) * 4;
    const float* Wm = W + (size_t)mx*HN*DN;
    float4 va = *(const float4*)(Wm + (size_t)(2*p)*DN + d4);
    float4 vb = *(const float4*)(Wm + (size_t)(2*p+1)*DN + d4);
    u32* O = g_wp + (size_t)(which*MN + mx)*64*1024;
    float a[4] = {va.x, va.y, va.z, va.w}, bq[4] = {vb.x, vb.y, vb.z, vb.w};
    int ix = pidx(p);
    #pragma unroll
    for (int e = 0; e < 4; e++){
        u32 hi, lo; packpair(a[e], bq[e], hi, lo);
        *(u64*)(O + (size_t)(d4+e)*1024 + ix) = (u64)hi | ((u64)lo<<32);
    }
}
__global__ void repack_v_kernel(){
    int flat = blockIdx.x*256 + threadIdx.x;
    int bm = blockIdx.y;
    int p = flat >> 4, d4 = (flat & 15) * 4;
    const float* V = g_v + (size_t)bm*TN*64;
    float4 va = *(const float4*)(V + (size_t)(2*p)*64 + d4);
    float4 vb = *(const float4*)(V + (size_t)(2*p+1)*64 + d4);
    u32* O = g_vp + (size_t)bm*64*1024;
    float a[4] = {va.x, va.y, va.z, va.w}, bq[4] = {vb.x, vb.y, vb.z, vb.w};
    int ix = pidx_hi(p);
    #pragma unroll
    for (int e = 0; e < 4; e++)
        O[(size_t)(d4+e)*1024 + ix] = packhi(a[e], bq[e]);
}

// ===== proj: 128 thr, R=2, NT-term fp16 mma, 32-k stages, cp.async ring =====
#define PJ_STG (128*36 + 64*36)
#define PJ_SMEM (PJ_STG*2*4)
template<int NT>
__global__ void __launch_bounds__(128,4) proj_kernel(){
    extern __shared__ u32 smu[];
    int tid = threadIdx.x, w = tid>>5, lane = tid&31, grp = lane>>2, tc = lane&3, rb = w*32;
    int qt = blockIdx.x, mx = blockIdx.y;
    int which, b;
    if (NT == 3){ which = 2; b = blockIdx.z; }
    else        { which = blockIdx.z & 1; b = blockIdx.z >> 1; }
    const u32* Ag = g_hsp + (size_t)(b*TN + qt*128)*1024;
    const u32* Wg = g_wp + (size_t)(which*MN + mx)*64*1024;
    u32 sbase = s2u(smu);

    {
        u32 bA = sbase, bW = sbase + 128*36*4;
        #pragma unroll
        for (int j = 0; j < 8; j++){ int u = j*128+tid, row = u>>3, q = (u&7)*4;
            cpa16(bA + (row*36 + q)*4, Ag + (size_t)row*1024 + q); }
        #pragma unroll
        for (int j = 0; j < 4; j++){ int u = j*128+tid, row = u>>3, q = (u&7)*4;
            cpa16(bW + (row*36 + q)*4, Wg + (size_t)row*1024 + q); }
        CPA_COMMIT();
    }

    float c[2][8][4] = {};
    for (int st = 0; st < 32; st++){
        __syncthreads();
        if (st+1 < 32){
            u32 bA = sbase + ((st+1)&1)*PJ_STG*4, bW = bA + 128*36*4;
            int off = (st+1)*32;
            #pragma unroll
            for (int j = 0; j < 8; j++){ int u = j*128+tid, row = u>>3, q = (u&7)*4;
                cpa16(bA + (row*36 + q)*4, Ag + (size_t)row*1024 + off + q); }
            #pragma unroll
            for (int j = 0; j < 4; j++){ int u = j*128+tid, row = u>>3, q = (u&7)*4;
                cpa16(bW + (row*36 + q)*4, Wg + (size_t)row*1024 + off + q); }
            CPA_COMMIT();
            CPA_WAIT1();
        } else {
            CPA_WAIT0();
        }
        __syncthreads();
        u32* sA = smu + (st&1)*PJ_STG;
        u32* sW = sA + 128*36;
        #pragma unroll
        for (int kc = 0; kc < 2; kc++){
            uint4 A0[2], A1[2];
            #pragma unroll
            for (int i = 0; i < 2; i++){
                A0[i] = *(uint4*)(sA + (rb+16*i+grp)*36 + kc*16 + tc*4);
                A1[i] = *(uint4*)(sA + (rb+16*i+grp+8)*36 + kc*16 + tc*4);
            }
            #pragma unroll
            for (int nt = 0; nt < 8; nt++){
                uint4 bb = *(uint4*)(sW + (nt*8+grp)*36 + kc*16 + tc*4);
                #pragma unroll
                for (int i = 0; i < 2; i++){
                    mma16(c[i][nt], A0[i].x, A1[i].x, A0[i].z, A1[i].z, bb.x, bb.z);
                    mma16(c[i][nt], A0[i].x, A1[i].x, A0[i].z, A1[i].z, bb.y, bb.w);
                    if (NT == 3)
                        mma16(c[i][nt], A0[i].y, A1[i].y, A0[i].w, A1[i].w, bb.x, bb.z);
                }
            }
        }
    }
    size_t rowbase = (size_t)(b*MN + mx)*TN + (size_t)qt*128;
    if (NT == 3){
        #pragma unroll
        for (int i = 0; i < 2; i++)
            #pragma unroll
            for (int nt = 0; nt < 8; nt++){
                int col = nt*8 + 2*tc;
                *(float2*)(g_v + (rowbase + rb+16*i+grp)*64 + col)   = make_float2(c[i][nt][0], c[i][nt][1]);
                *(float2*)(g_v + (rowbase + rb+16*i+grp+8)*64 + col) = make_float2(c[i][nt][2], c[i][nt][3]);
            }
    } else {
        u32* O = (which==0 ? g_qp : g_kp) + rowbase*64;
        float sc = (which==0) ? 0.125f : 1.0f;
        #pragma unroll
        for (int i = 0; i < 2; i++)
            #pragma unroll
            for (int nt = 0; nt < 8; nt++){
                int ix = ((nt>>1)<<4) + tc*4 + 2*(nt&1);
                u32 hi, lo;
                packpair(c[i][nt][0]*sc, c[i][nt][1]*sc, hi, lo);
                *(u64*)(O + (size_t)(rb+16*i+grp)*64 + ix) = (u64)hi | ((u64)lo<<32);
                packpair(c[i][nt][2]*sc, c[i][nt][3]*sc, hi, lo);
                *(u64*)(O + (size_t)(rb+16*i+grp+8)*64 + ix) = (u64)hi | ((u64)lo<<32);
            }
    }
}

// ===== attention: q128 (R=2), k64, no max-sub, QK 2-term, PV 1-term (V hi) =====
#define AT_BUF (64*68 + 64*36)          // K + V(hi) per stage (u32) = 6656
#define AT_SMEM ((AT_BUF*2 + 128*36)*4) // 71680 B
__global__ void __launch_bounds__(128,3) attn_kernel(float* __restrict__ out_sha){
    extern __shared__ u32 smu[];
    u32* sP = smu + AT_BUF*2;
    int tid = threadIdx.x, w = tid>>5, lane = tid&31, grp = lane>>2, tc = lane&3, rb = w*32;
    int qt = blockIdx.x, m = blockIdx.y, b = blockIdx.z, bm = b*MN + m;
    const u32* Qg = g_qp + ((size_t)bm*TN + (size_t)qt*128)*64;
    const u32* Kg = g_kp + (size_t)bm*TN*64;
    const u32* Vg = g_vp + (size_t)bm*64*1024;
    u32 sbase = s2u(smu);

    {
        u32 bK = sbase, bV = sbase + 64*68*4;
        #pragma unroll
        for (int j = 0; j < 8; j++){ int u = j*128+tid, row = u>>4, q = (u&15)*4;
            cpa16(bK + (row*68 + q)*4, Kg + (size_t)row*64 + q); }
        #pragma unroll
        for (int j = 0; j < 4; j++){ int u = j*128+tid, row = u>>3, q = (u&7)*4;
            cpa16(bV + (row*36 + q)*4, Vg + (size_t)row*1024 + q); }
        CPA_COMMIT();
    }

    u32 qh[2][4][4];
    #pragma unroll
    for (int i = 0; i < 2; i++)
        #pragma unroll
        for (int kc = 0; kc < 4; kc++){
            uint4 r0 = *(const uint4*)(Qg + (size_t)(rb+16*i+grp)*64 + kc*16 + tc*4);
            uint4 r1 = *(const uint4*)(Qg + (size_t)(rb+16*i+grp+8)*64 + kc*16 + tc*4);
            qh[i][kc][0]=r0.x; qh[i][kc][1]=r1.x; qh[i][kc][2]=r0.z; qh[i][kc][3]=r1.z;
        }

    float o[2][8][4] = {};
    float lsum[2][2] = {}, tsum[2][2] = {};

    for (int kt = 0; kt < TN/64; kt++){
        __syncthreads();
        if (kt+1 < TN/64){
            u32 bK = sbase + ((kt+1)&1)*AT_BUF*4, bV = bK + 64*68*4;
            #pragma unroll
            for (int j = 0; j < 8; j++){ int u = j*128+tid, row = u>>4, q = (u&15)*4;
                cpa16(bK + (row*68 + q)*4, Kg + (size_t)((kt+1)*64+row)*64 + q); }
            #pragma unroll
            for (int j = 0; j < 4; j++){ int u = j*128+tid, row = u>>3, q = (u&7)*4;
                cpa16(bV + (row*36 + q)*4, Vg + (size_t)row*1024 + (kt+1)*32 + q); }
            CPA_COMMIT();
            CPA_WAIT1();
        } else {
            CPA_WAIT0();
        }
        __syncthreads();
        u32* sK = smu + (kt&1)*AT_BUF;
        u32* sV = sK + 64*68;

        #pragma unroll
        for (int nt = 0; nt < 8; nt++){
            float s0[4] = {}, s1[4] = {};
            #pragma unroll
            for (int kc = 0; kc < 4; kc++){
                uint4 bb = *(uint4*)(sK + (nt*8+grp)*68 + kc*16 + tc*4);
                mma16(s0, qh[0][kc][0], qh[0][kc][1], qh[0][kc][2], qh[0][kc][3], bb.x, bb.z);
                mma16(s0, qh[0][kc][0], qh[0][kc][1], qh[0][kc][2], qh[0][kc][3], bb.y, bb.w);
                mma16(s1, qh[1][kc][0], qh[1][kc][1], qh[1][kc][2], qh[1][kc][3], bb.x, bb.z);
                mma16(s1, qh[1][kc][0], qh[1][kc][1], qh[1][kc][2], qh[1][kc][3], bb.y, bb.w);
            }
            int ix = ((nt>>1)<<3) + 2*tc + (nt&1);
            #pragma unroll
            for (int i = 0; i < 2; i++){
                float* s = i ? s1 : s0;
                float p0 = __expf(s[0]), p1 = __expf(s[1]);
                float p2 = __expf(s[2]), p3 = __expf(s[3]);
                lsum[i][0] += p0 + p1; tsum[i][0] += p0*s[0] + p1*s[1];
                lsum[i][1] += p2 + p3; tsum[i][1] += p2*s[2] + p3*s[3];
                sP[(rb+16*i+grp)*36 + ix]   = packhi(p0, p1);
                sP[(rb+16*i+grp+8)*36 + ix] = packhi(p2, p3);
            }
        }
        __syncwarp();

        #pragma unroll
        for (int kc = 0; kc < 4; kc++){
            uint2 P0[2], P1[2];
            #pragma unroll
            for (int i = 0; i < 2; i++){
                P0[i] = *(uint2*)(sP + (rb+16*i+grp)*36 + kc*8 + 2*tc);
                P1[i] = *(uint2*)(sP + (rb+16*i+grp+8)*36 + kc*8 + 2*tc);
            }
            #pragma unroll
            for (int nt = 0; nt < 8; nt++){
                uint2 bb = *(uint2*)(sV + (nt*8+grp)*36 + kc*8 + 2*tc);
                #pragma unroll
                for (int i = 0; i < 2; i++)
                    mma16(o[i][nt], P0[i].x, P1[i].x, P0[i].y, P1[i].y, bb.x, bb.y);
            }
        }
        __syncwarp();
    }

    #pragma unroll
    for (int i = 0; i < 2; i++)
        #pragma unroll
        for (int h = 0; h < 2; h++){
            lsum[i][h] += __shfl_xor_sync(0xffffffffu, lsum[i][h], 1);
            lsum[i][h] += __shfl_xor_sync(0xffffffffu, lsum[i][h], 2);
            tsum[i][h] += __shfl_xor_sync(0xffffffffu, tsum[i][h], 1);
            tsum[i][h] += __shfl_xor_sync(0xffffffffu, tsum[i][h], 2);
        }
    #pragma unroll
    for (int i = 0; i < 2; i++){
        float inv0 = 1.f/lsum[i][0], inv1 = 1.f/lsum[i][1];
        size_t t0 = (size_t)qt*128 + rb + 16*i + grp;
        float* op0 = out_sha + (((size_t)b*TN + t0)*MN + m)*DN;
        float* op1 = out_sha + (((size_t)b*TN + t0 + 8)*MN + m)*DN;
        #pragma unroll
        for (int nt = 0; nt < 8; nt++){
            int col = nt*8 + 2*tc;
            *(float2*)(op0 + col) = make_float2(o[i][nt][0]*inv0, o[i][nt][1]*inv0);
            *(float2*)(op1 + col) = make_float2(o[i][nt][2]*inv1, o[i][nt][3]*inv1);
        }
    }
    float e = 0.f;
    #pragma unroll
    for (int i = 0; i < 2; i++)
        #pragma unroll
        for (int h = 0; h < 2; h++)
            e += logf(lsum[i][h]) - tsum[i][h]/lsum[i][h];
    #pragma unroll
    for (int off = 16; off; off >>= 1) e += __shfl_xor_sync(0xffffffffu, e, off);
    if (lane == 0) atomicAdd(&g_ent[bm], (double)(e * 0.25f));
}

// ===== gating =====
__global__ void gate_kernel(const float* __restrict__ gates, float* __restrict__ out){
    __shared__ int cnt;
    int tid = threadIdx.x;
    if (tid == 0) cnt = 0;
    __syncthreads();
    int m = tid & 15;
    float aff = -(float)(g_ent[tid] * (1.0 / (double)TN));
    float s = aff;
    #pragma unroll
    for (int off = 8; off; off >>= 1) s += __shfl_xor_sync(0xffffffffu, s, off);
    float mu = s * (1.f/16.f);
    float d = aff - mu, v = d*d;
    #pragma unroll
    for (int off = 8; off; off >>= 1) v += __shfl_xor_sync(0xffffffffu, v, off);
    float sd = sqrtf(v * (1.f/15.f));
    float norm = d / (sd + 1e-9f);
    float logit = norm - 1.f/(1.f + expf(-gates[m]));
    float hard = (logit > 0.f) ? 1.f : 0.f;
    float nact = hard;
    #pragma unroll
    for (int off = 8; off; off >>= 1) nact += __shfl_xor_sync(0xffffffffu, nact, off);
    bool inactive = (nact == 0.f);
    float v1 = norm; int i1 = m;
    #pragma unroll
    for (int off = 8; off; off >>= 1){
        float ov = __shfl_xor_sync(0xffffffffu, v1, off);
        int oi = __shfl_xor_sync(0xffffffffu, i1, off);
        if (ov > v1 || (ov == v1 && oi < i1)){ v1 = ov; i1 = oi; }
    }
    float v2 = (m == i1) ? -INFINITY : norm; int i2 = m;
    #pragma unroll
    for (int off = 8; off; off >>= 1){
        float ov = __shfl_xor_sync(0xffffffffu, v2, off);
        int oi = __shfl_xor_sync(0xffffffffu, i2, off);
        if (ov > v2 || (ov == v2 && oi < i2)){ v2 = ov; i2 = oi; }
    }
    float mask = hard;
    if (inactive && (m == i1 || m == i2)) mask = 1.f;
    float na = mask;
    #pragma unroll
    for (int off = 8; off; off >>= 1) na += __shfl_xor_sync(0xffffffffu, na, off);
    float nm = mask / fmaxf(na, 1.f);
    out[OFF_LOGIT + tid] = logit;
    out[OFF_MASK + tid] = mask;
    g_nmask[tid] = nm;
    if (m == 0 && inactive) atomicAdd(&cnt, 1);
    __syncthreads();
    if (tid == 0) out[OFF_FBC] = (float)cnt;
}

// ===== combine / oproj / final =====
__global__ void combine_kernel(const float* __restrict__ sha){
    __shared__ float snm[32];
    if (threadIdx.x < 32) snm[threadIdx.x] = g_nmask[threadIdx.x];
    __syncthreads();
    int idx4 = blockIdx.x*256 + threadIdx.x;
    int d4 = (idx4 & 15) << 2, t = (idx4 >> 4) & (TN-1), b = idx4 >> 15;
    const float* base = sha + ((size_t)(b*TN + t)*MN)*DN + d4;
    const float* w = snm + b*16;
    float4 acc = make_float4(0.f,0.f,0.f,0.f);
    #pragma unroll
    for (int mm = 0; mm < MN; mm++){
        float4 v = *(const float4*)(base + mm*DN);
        float wm = w[mm];
        acc.x = fmaf(v.x,wm,acc.x); acc.y = fmaf(v.y,wm,acc.y);
        acc.z = fmaf(v.z,wm,acc.z); acc.w = fmaf(v.w,wm,acc.w);
    }
    *(float4*)(g_comb + (size_t)idx4*4) = acc;
}
__global__ void oproj_kernel(const float* __restrict__ ow){
    __shared__ float snm[32];
    if (threadIdx.x < 32) snm[threadIdx.x] = g_nmask[threadIdx.x];
    __syncthreads();
    int idx4 = blockIdx.x*256 + threadIdx.x;
    int h4 = (idx4 & 255) << 2, dd = (idx4 >> 8) & 63, b = idx4 >> 14;
    float4 acc = make_float4(0.f,0.f,0.f,0.f);
    #pragma unroll
    for (int mm = 0; mm < MN; mm++){
        float4 v = *(const float4*)(ow + ((size_t)mm*DN + dd)*HN + h4);
        float wm = snm[b*16 + mm];
        acc.x = fmaf(v.x,wm,acc.x); acc.y = fmaf(v.y,wm,acc.y);
        acc.z = fmaf(v.z,wm,acc.z); acc.w = fmaf(v.w,wm,acc.w);
    }
    *(float4*)(g_oproj + (size_t)idx4*4) = acc;
}
__global__ void final_kernel(float* __restrict__ out){
    __shared__ float smem[16*68 + 16*64];
    float* sAt = smem;
    float* sB = smem + 16*68;
    int tid = threadIdx.x;
    int r0 = (tid >> 4) << 2, c0 = (tid & 15) << 2;
    int arow = tid >> 2, ak = (tid & 3) << 2;
    int wkr = tid >> 4, wn = (tid & 15) << 2;
    int ht = blockIdx.x, qt = blockIdx.y, b = blockIdx.z;
    const float* A = g_comb + (size_t)b*TN*DN + (size_t)qt*64*DN;
    const float* W = g_oproj + (size_t)b*DN*HN + ht*64;
    float* C = out + (size_t)b*TN*HN + (size_t)qt*64*HN + ht*64;
    u64 acc2[4][2] = {};
    for (int k0 = 0; k0 < DN; k0 += 16){
        __syncthreads();
        float4 av = *(const float4*)(A + (size_t)arow*DN + k0 + ak);
        sAt[(ak+0)*68+arow]=av.x; sAt[(ak+1)*68+arow]=av.y;
        sAt[(ak+2)*68+arow]=av.z; sAt[(ak+3)*68+arow]=av.w;
        *(float4*)(sB + wkr*64 + wn) = *(const float4*)(W + (size_t)(k0+wkr)*HN + wn);
        __syncthreads();
        #pragma unroll
        for (int kk = 0; kk < 16; kk++){
            float4 a4 = *(const float4*)(sAt + kk*68 + r0);
            ulonglong2 bu = *(const ulonglong2*)(sB + kk*64 + c0);
            u64 a0 = pk2f(a4.x,a4.x), a1 = pk2f(a4.y,a4.y);
            u64 a2 = pk2f(a4.z,a4.z), a3 = pk2f(a4.w,a4.w);
            ffma2(acc2[0][0],a0,bu.x); ffma2(acc2[0][1],a0,bu.y);
            ffma2(acc2[1][0],a1,bu.x); ffma2(acc2[1][1],a1,bu.y);
            ffma2(acc2[2][0],a2,bu.x); ffma2(acc2[2][1],a2,bu.y);
            ffma2(acc2[3][0],a3,bu.x); ffma2(acc2[3][1],a3,bu.y);
        }
    }
    #pragma unroll
    for (int i = 0; i < 4; i++){
        float4 o;
        upk2f(o.x,o.y,acc2[i][0]); upk2f(o.z,o.w,acc2[i][1]);
        *(float4*)(C + (size_t)(r0+i)*HN + c0) = o;
    }
}

extern "C" void kernel_launch(void* const* d_in, const int* in_sizes, int n_in,
                              void* d_out, int out_size)
{
    const float* hs    = (const float*)d_in[0];
    const float* wq    = (const float*)d_in[1];
    const float* wk    = (const float*)d_in[2];
    const float* wv    = (const float*)d_in[3];
    const float* ow    = (const float*)d_in[4];
    const float* gates = (const float*)d_in[5];
    float* out = (float*)d_out;

    cudaFuncSetAttribute(proj_kernel<2>, cudaFuncAttributeMaxDynamicSharedMemorySize, PJ_SMEM);
    cudaFuncSetAttribute(proj_kernel<3>, cudaFuncAttributeMaxDynamicSharedMemorySize, PJ_SMEM);
    cudaFuncSetAttribute(attn_kernel, cudaFuncAttributeMaxDynamicSharedMemorySize, AT_SMEM);

    init_kernel<<<1, 32>>>();
    split_hs_kernel<<<BN*TN, 256>>>(hs);
    split_w_kernel<<<dim3(512, 3), 256>>>(wq, wk, wv);
    proj_kernel<3><<<dim3(16, 16, 2), 128, PJ_SMEM>>>();   // V (3-term)
    proj_kernel<2><<<dim3(16, 16, 4), 128, PJ_SMEM>>>();   // Q,K (2-term)
    repack_v_kernel<<<dim3(64, 32), 256>>>();
    attn_kernel<<<dim3(16, 16, 2), 128, AT_SMEM>>>(out + OFF_SHA);
    gate_kernel<<<1, 32>>>(gates, out);
    combine_kernel<<<256, 256>>>(out + OFF_SHA);
    oproj_kernel<<<128, 256>>>(ow);
    final_kernel<<<dim3(16, 32, 2), 256>>>(out);
}

// round 16
// speedup vs baseline: 1.4462x; 1.0501x over previous
#include <cuda_runtime.h>
#include <cuda_fp16.h>
#include <math.h>

#define BN 2
#define TN 2048
#define HN 1024
#define DN 64
#define MN 16
#define QKV_ELEMS (BN*MN*TN*DN)
typedef unsigned long long u64;
typedef unsigned int u32;

__device__ __forceinline__ void mma16(float* d, u32 a0, u32 a1, u32 a2, u32 a3, u32 b0, u32 b1){
    asm volatile("mma.sync.aligned.m16n8k16.row.col.f32.f16.f16.f32 "
        "{%0,%1,%2,%3},{%4,%5,%6,%7},{%8,%9},{%0,%1,%2,%3};"
        : "+f"(d[0]),"+f"(d[1]),"+f"(d[2]),"+f"(d[3])
        : "r"(a0),"r"(a1),"r"(a2),"r"(a3),"r"(b0),"r"(b1));
}
__device__ __forceinline__ void packpair(float v0, float v1, u32& hi, u32& lo){
    __half h0 = __float2half_rn(v0), h1 = __float2half_rn(v1);
    __half2 H = __halves2half2(h0, h1);
    __half2 L = __halves2half2(__float2half_rn(v0 - __half2float(h0)),
                               __float2half_rn(v1 - __half2float(h1)));
    hi = *(u32*)&H; lo = *(u32*)&L;
}
__device__ __forceinline__ u32 packhi(float v0, float v1){
    __half2 H = __halves2half2(__float2half_rn(v0), __float2half_rn(v1));
    return *(u32*)&H;
}
__device__ __forceinline__ int pidx(int p){
    return ((p>>3)<<4) + ((p&3)<<2) + (((p>>2)&1)<<1);
}
__device__ __forceinline__ int pidx_hi(int p){
    return ((p>>3)<<3) + ((p&3)<<1) + ((p>>2)&1);
}
__device__ __forceinline__ u64 pk2f(float lo, float hi){
    u64 r; asm("mov.b64 %0, {%1,%2};" : "=l"(r) : "f"(lo), "f"(hi)); return r;
}
__device__ __forceinline__ void upk2f(float& lo, float& hi, u64 v){
    asm("mov.b64 {%0,%1}, %2;" : "=f"(lo), "=f"(hi) : "l"(v));
}
__device__ __forceinline__ void ffma2(u64& d, u64 a, u64 b){
    asm("fma.rn.f32x2 %0, %1, %2, %0;" : "+l"(d) : "l"(a), "l"(b));
}
__device__ __forceinline__ u32 s2u(const void* p){
    u32 a; asm("{ .reg .u64 t; cvta.to.shared.u64 t, %1; cvt.u32.u64 %0, t; }":"=r"(a):"l"(p)); return a;
}
__device__ __forceinline__ void cpa16(u32 dst, const void* src){
    asm volatile("cp.async.cg.shared.global [%0], [%1], 16;" :: "r"(dst), "l"(src) : "memory");
}
#define CPA_COMMIT() asm volatile("cp.async.commit_group;" ::: "memory")
#define CPA_WAIT1()  asm volatile("cp.async.wait_group 1;" ::: "memory")
#define CPA_WAIT0()  asm volatile("cp.async.wait_group 0;" ::: "memory")

__device__ u32   g_hsp[BN*TN*1024];
__device__ u32   g_wp[3*MN*64*1024];
__device__ u32   g_qp[BN*MN*TN*64];
__device__ u32   g_kp[BN*MN*TN*64];
__device__ float g_v[QKV_ELEMS];
__device__ u32   g_vp[BN*MN*64*1024];
__device__ double g_ent[BN*MN];
__device__ float g_nmask[BN*MN];
__device__ float g_comb[BN*TN*DN];
__device__ float g_oproj[BN*DN*HN];

#define OFF_SHA   (BN*TN*HN)
#define OFF_LOGIT (OFF_SHA + BN*TN*MN*DN)
#define OFF_MASK  (OFF_LOGIT + BN*MN)
#define OFF_FBC   (OFF_MASK + BN*MN)

__global__ void init_kernel(){ g_ent[threadIdx.x] = 0.0; }

__global__ void split_hs_kernel(const float* __restrict__ hs){
    int row = blockIdx.x, t = threadIdx.x;
    float4 v = *(const float4*)(hs + (size_t)row*1024 + t*4);
    u32 hi, lo;
    u32* O = g_hsp + (size_t)row*1024;
    packpair(v.x, v.y, hi, lo); *(u64*)(O + pidx(2*t))   = (u64)hi | ((u64)lo<<32);
    packpair(v.z, v.w, hi, lo); *(u64*)(O + pidx(2*t+1)) = (u64)hi | ((u64)lo<<32);
}
__global__ void split_w_kernel(const float* __restrict__ wq, const float* __restrict__ wk,
                               const float* __restrict__ wv){
    int which = blockIdx.y;
    const float* W = which==0 ? wq : which==1 ? wk : wv;
    int flat = blockIdx.x*256 + threadIdx.x;
    int mx = flat >> 13, r = flat & 8191, p = r >> 4, d4 = (r & 15) * 4;
    const float* Wm = W + (size_t)mx*HN*DN;
    float4 va = *(const float4*)(Wm + (size_t)(2*p)*DN + d4);
    float4 vb = *(const float4*)(Wm + (size_t)(2*p+1)*DN + d4);
    u32* O = g_wp + (size_t)(which*MN + mx)*64*1024;
    float a[4] = {va.x, va.y, va.z, va.w}, bq[4] = {vb.x, vb.y, vb.z, vb.w};
    int ix = pidx(p);
    #pragma unroll
    for (int e = 0; e < 4; e++){
        u32 hi, lo; packpair(a[e], bq[e], hi, lo);
        *(u64*)(O + (size_t)(d4+e)*1024 + ix) = (u64)hi | ((u64)lo<<32);
    }
}
__global__ void repack_v_kernel(){
    int flat = blockIdx.x*256 + threadIdx.x;
    int bm = blockIdx.y;
    int p = flat >> 4, d4 = (flat & 15) * 4;
    const float* V = g_v + (size_t)bm*TN*64;
    float4 va = *(const float4*)(V + (size_t)(2*p)*64 + d4);
    float4 vb = *(const float4*)(V + (size_t)(2*p+1)*64 + d4);
    u32* O = g_vp + (size_t)bm*64*1024;
    float a[4] = {va.x, va.y, va.z, va.w}, bq[4] = {vb.x, vb.y, vb.z, vb.w};
    int ix = pidx_hi(p);
    #pragma unroll
    for (int e = 0; e < 4; e++)
        O[(size_t)(d4+e)*1024 + ix] = packhi(a[e], bq[e]);
}

// ===== proj: 128 thr, R=2, NT-term fp16 mma, 32-k stages, cp.async ring =====
#define PJ_STG (128*36 + 64*36)
#define PJ_SMEM (PJ_STG*2*4)
template<int NT>
__global__ void __launch_bounds__(128,4) proj_kernel(){
    extern __shared__ u32 smu[];
    int tid = threadIdx.x, w = tid>>5, lane = tid&31, grp = lane>>2, tc = lane&3, rb = w*32;
    int qt = blockIdx.x, mx = blockIdx.y;
    int which, b;
    if (NT == 3){ which = 2; b = blockIdx.z; }
    else        { which = blockIdx.z & 1; b = blockIdx.z >> 1; }
    const u32* Ag = g_hsp + (size_t)(b*TN + qt*128)*1024;
    const u32* Wg = g_wp + (size_t)(which*MN + mx)*64*1024;
    u32 sbase = s2u(smu);

    {
        u32 bA = sbase, bW = sbase + 128*36*4;
        #pragma unroll
        for (int j = 0; j < 8; j++){ int u = j*128+tid, row = u>>3, q = (u&7)*4;
            cpa16(bA + (row*36 + q)*4, Ag + (size_t)row*1024 + q); }
        #pragma unroll
        for (int j = 0; j < 4; j++){ int u = j*128+tid, row = u>>3, q = (u&7)*4;
            cpa16(bW + (row*36 + q)*4, Wg + (size_t)row*1024 + q); }
        CPA_COMMIT();
    }

    float c[2][8][4] = {};
    for (int st = 0; st < 32; st++){
        __syncthreads();
        if (st+1 < 32){
            u32 bA = sbase + ((st+1)&1)*PJ_STG*4, bW = bA + 128*36*4;
            int off = (st+1)*32;
            #pragma unroll
            for (int j = 0; j < 8; j++){ int u = j*128+tid, row = u>>3, q = (u&7)*4;
                cpa16(bA + (row*36 + q)*4, Ag + (size_t)row*1024 + off + q); }
            #pragma unroll
            for (int j = 0; j < 4; j++){ int u = j*128+tid, row = u>>3, q = (u&7)*4;
                cpa16(bW + (row*36 + q)*4, Wg + (size_t)row*1024 + off + q); }
            CPA_COMMIT();
            CPA_WAIT1();
        } else {
            CPA_WAIT0();
        }
        __syncthreads();
        u32* sA = smu + (st&1)*PJ_STG;
        u32* sW = sA + 128*36;
        #pragma unroll
        for (int kc = 0; kc < 2; kc++){
            uint4 A0[2], A1[2];
            #pragma unroll
            for (int i = 0; i < 2; i++){
                A0[i] = *(uint4*)(sA + (rb+16*i+grp)*36 + kc*16 + tc*4);
                A1[i] = *(uint4*)(sA + (rb+16*i+grp+8)*36 + kc*16 + tc*4);
            }
            #pragma unroll
            for (int nt = 0; nt < 8; nt++){
                uint4 bb = *(uint4*)(sW + (nt*8+grp)*36 + kc*16 + tc*4);
                #pragma unroll
                for (int i = 0; i < 2; i++){
                    mma16(c[i][nt], A0[i].x, A1[i].x, A0[i].z, A1[i].z, bb.x, bb.z);
                    mma16(c[i][nt], A0[i].x, A1[i].x, A0[i].z, A1[i].z, bb.y, bb.w);
                    if (NT == 3)
                        mma16(c[i][nt], A0[i].y, A1[i].y, A0[i].w, A1[i].w, bb.x, bb.z);
                }
            }
        }
    }
    size_t rowbase = (size_t)(b*MN + mx)*TN + (size_t)qt*128;
    if (NT == 3){
        #pragma unroll
        for (int i = 0; i < 2; i++)
            #pragma unroll
            for (int nt = 0; nt < 8; nt++){
                int col = nt*8 + 2*tc;
                *(float2*)(g_v + (rowbase + rb+16*i+grp)*64 + col)   = make_float2(c[i][nt][0], c[i][nt][1]);
                *(float2*)(g_v + (rowbase + rb+16*i+grp+8)*64 + col) = make_float2(c[i][nt][2], c[i][nt][3]);
            }
    } else {
        u32* O = (which==0 ? g_qp : g_kp) + rowbase*64;
        float sc = (which==0) ? 0.125f : 1.0f;
        #pragma unroll
        for (int i = 0; i < 2; i++)
            #pragma unroll
            for (int nt = 0; nt < 8; nt++){
                int ix = ((nt>>1)<<4) + tc*4 + 2*(nt&1);
                u32 hi, lo;
                packpair(c[i][nt][0]*sc, c[i][nt][1]*sc, hi, lo);
                *(u64*)(O + (size_t)(rb+16*i+grp)*64 + ix) = (u64)hi | ((u64)lo<<32);
                packpair(c[i][nt][2]*sc, c[i][nt][3]*sc, hi, lo);
                *(u64*)(O + (size_t)(rb+16*i+grp+8)*64 + ix) = (u64)hi | ((u64)lo<<32);
            }
    }
}

// ===== attention: q128 (R=2), k64, QK 2-term, PV 1-term, P in registers =====
#define AT_BUF (64*68 + 64*36)          // K + V(hi) per stage (u32)
#define AT_SMEM (AT_BUF*2*4)            // 53248 B
__global__ void __launch_bounds__(128,3) attn_kernel(float* __restrict__ out_sha){
    extern __shared__ u32 smu[];
    int tid = threadIdx.x, w = tid>>5, lane = tid&31, grp = lane>>2, tc = lane&3, rb = w*32;
    int qt = blockIdx.x, m = blockIdx.y, b = blockIdx.z, bm = b*MN + m;
    const u32* Qg = g_qp + ((size_t)bm*TN + (size_t)qt*128)*64;
    const u32* Kg = g_kp + (size_t)bm*TN*64;
    const u32* Vg = g_vp + (size_t)bm*64*1024;
    u32 sbase = s2u(smu);

    {
        u32 bK = sbase, bV = sbase + 64*68*4;
        #pragma unroll
        for (int j = 0; j < 8; j++){ int u = j*128+tid, row = u>>4, q = (u&15)*4;
            cpa16(bK + (row*68 + q)*4, Kg + (size_t)row*64 + q); }
        #pragma unroll
        for (int j = 0; j < 4; j++){ int u = j*128+tid, row = u>>3, q = (u&7)*4;
            cpa16(bV + (row*36 + q)*4, Vg + (size_t)row*1024 + q); }
        CPA_COMMIT();
    }

    u32 qh[2][4][4];
    #pragma unroll
    for (int i = 0; i < 2; i++)
        #pragma unroll
        for (int kc = 0; kc < 4; kc++){
            uint4 r0 = *(const uint4*)(Qg + (size_t)(rb+16*i+grp)*64 + kc*16 + tc*4);
            uint4 r1 = *(const uint4*)(Qg + (size_t)(rb+16*i+grp+8)*64 + kc*16 + tc*4);
            qh[i][kc][0]=r0.x; qh[i][kc][1]=r1.x; qh[i][kc][2]=r0.z; qh[i][kc][3]=r1.z;
        }

    float o[2][8][4] = {};
    float lsum[2][2] = {}, tsum[2][2] = {};

    for (int kt = 0; kt < TN/64; kt++){
        __syncthreads();
        if (kt+1 < TN/64){
            u32 bK = sbase + ((kt+1)&1)*AT_BUF*4, bV = bK + 64*68*4;
            #pragma unroll
            for (int j = 0; j < 8; j++){ int u = j*128+tid, row = u>>4, q = (u&15)*4;
                cpa16(bK + (row*68 + q)*4, Kg + (size_t)((kt+1)*64+row)*64 + q); }
            #pragma unroll
            for (int j = 0; j < 4; j++){ int u = j*128+tid, row = u>>3, q = (u&7)*4;
                cpa16(bV + (row*36 + q)*4, Vg + (size_t)row*1024 + (kt+1)*32 + q); }
            CPA_COMMIT();
            CPA_WAIT1();
        } else {
            CPA_WAIT0();
        }
        __syncthreads();
        u32* sK = smu + (kt&1)*AT_BUF;
        u32* sV = sK + 64*68;

        // QK -> exp -> P fragments in registers (D layout == PV A layout)
        u32 pf[2][4][4];
        #pragma unroll
        for (int nt = 0; nt < 8; nt++){
            float s0[4] = {}, s1[4] = {};
            #pragma unroll
            for (int kc = 0; kc < 4; kc++){
                uint4 bb = *(uint4*)(sK + (nt*8+grp)*68 + kc*16 + tc*4);
                mma16(s0, qh[0][kc][0], qh[0][kc][1], qh[0][kc][2], qh[0][kc][3], bb.x, bb.z);
                mma16(s0, qh[0][kc][0], qh[0][kc][1], qh[0][kc][2], qh[0][kc][3], bb.y, bb.w);
                mma16(s1, qh[1][kc][0], qh[1][kc][1], qh[1][kc][2], qh[1][kc][3], bb.x, bb.z);
                mma16(s1, qh[1][kc][0], qh[1][kc][1], qh[1][kc][2], qh[1][kc][3], bb.y, bb.w);
            }
            int kcp = nt >> 1, hf = (nt & 1) << 1;
            #pragma unroll
            for (int i = 0; i < 2; i++){
                float* s = i ? s1 : s0;
                float p0 = __expf(s[0]), p1 = __expf(s[1]);
                float p2 = __expf(s[2]), p3 = __expf(s[3]);
                lsum[i][0] += p0 + p1; tsum[i][0] += p0*s[0] + p1*s[1];
                lsum[i][1] += p2 + p3; tsum[i][1] += p2*s[2] + p3*s[3];
                pf[i][kcp][hf]     = packhi(p0, p1);
                pf[i][kcp][hf + 1] = packhi(p2, p3);
            }
        }

        // O += P V (P from registers, V hi-only)
        #pragma unroll
        for (int kcp = 0; kcp < 4; kcp++)
            #pragma unroll
            for (int dt = 0; dt < 8; dt++){
                uint2 bb = *(uint2*)(sV + (dt*8+grp)*36 + kcp*8 + 2*tc);
                #pragma unroll
                for (int i = 0; i < 2; i++)
                    mma16(o[i][dt], pf[i][kcp][0], pf[i][kcp][1], pf[i][kcp][2], pf[i][kcp][3], bb.x, bb.y);
            }
    }

    #pragma unroll
    for (int i = 0; i < 2; i++)
        #pragma unroll
        for (int h = 0; h < 2; h++){
            lsum[i][h] += __shfl_xor_sync(0xffffffffu, lsum[i][h], 1);
            lsum[i][h] += __shfl_xor_sync(0xffffffffu, lsum[i][h], 2);
            tsum[i][h] += __shfl_xor_sync(0xffffffffu, tsum[i][h], 1);
            tsum[i][h] += __shfl_xor_sync(0xffffffffu, tsum[i][h], 2);
        }
    #pragma unroll
    for (int i = 0; i < 2; i++){
        float inv0 = 1.f/lsum[i][0], inv1 = 1.f/lsum[i][1];
        size_t t0 = (size_t)qt*128 + rb + 16*i + grp;
        float* op0 = out_sha + (((size_t)b*TN + t0)*MN + m)*DN;
        float* op1 = out_sha + (((size_t)b*TN + t0 + 8)*MN + m)*DN;
        #pragma unroll
        for (int nt = 0; nt < 8; nt++){
            int col = nt*8 + 2*tc;
            *(float2*)(op0 + col) = make_float2(o[i][nt][0]*inv0, o[i][nt][1]*inv0);
            *(float2*)(op1 + col) = make_float2(o[i][nt][2]*inv1, o[i][nt][3]*inv1);
        }
    }
    float e = 0.f;
    #pragma unroll
    for (int i = 0; i < 2; i++)
        #pragma unroll
        for (int h = 0; h < 2; h++)
            e += logf(lsum[i][h]) - tsum[i][h]/lsum[i][h];
    #pragma unroll
    for (int off = 16; off; off >>= 1) e += __shfl_xor_sync(0xffffffffu, e, off);
    if (lane == 0) atomicAdd(&g_ent[bm], (double)(e * 0.25f));
}

// ===== gating =====
__global__ void gate_kernel(const float* __restrict__ gates, float* __restrict__ out){
    __shared__ int cnt;
    int tid = threadIdx.x;
    if (tid == 0) cnt = 0;
    __syncthreads();
    int m = tid & 15;
    float aff = -(float)(g_ent[tid] * (1.0 / (double)TN));
    float s = aff;
    #pragma unroll
    for (int off = 8; off; off >>= 1) s += __shfl_xor_sync(0xffffffffu, s, off);
    float mu = s * (1.f/16.f);
    float d = aff - mu, v = d*d;
    #pragma unroll
    for (int off = 8; off; off >>= 1) v += __shfl_xor_sync(0xffffffffu, v, off);
    float sd = sqrtf(v * (1.f/15.f));
    float norm = d / (sd + 1e-9f);
    float logit = norm - 1.f/(1.f + expf(-gates[m]));
    float hard = (logit > 0.f) ? 1.f : 0.f;
    float nact = hard;
    #pragma unroll
    for (int off = 8; off; off >>= 1) nact += __shfl_xor_sync(0xffffffffu, nact, off);
    bool inactive = (nact == 0.f);
    float v1 = norm; int i1 = m;
    #pragma unroll
    for (int off = 8; off; off >>= 1){
        float ov = __shfl_xor_sync(0xffffffffu, v1, off);
        int oi = __shfl_xor_sync(0xffffffffu, i1, off);
        if (ov > v1 || (ov == v1 && oi < i1)){ v1 = ov; i1 = oi; }
    }
    float v2 = (m == i1) ? -INFINITY : norm; int i2 = m;
    #pragma unroll
    for (int off = 8; off; off >>= 1){
        float ov = __shfl_xor_sync(0xffffffffu, v2, off);
        int oi = __shfl_xor_sync(0xffffffffu, i2, off);
        if (ov > v2 || (ov == v2 && oi < i2)){ v2 = ov; i2 = oi; }
    }
    float mask = hard;
    if (inactive && (m == i1 || m == i2)) mask = 1.f;
    float na = mask;
    #pragma unroll
    for (int off = 8; off; off >>= 1) na += __shfl_xor_sync(0xffffffffu, na, off);
    float nm = mask / fmaxf(na, 1.f);
    out[OFF_LOGIT + tid] = logit;
    out[OFF_MASK + tid] = mask;
    g_nmask[tid] = nm;
    if (m == 0 && inactive) atomicAdd(&cnt, 1);
    __syncthreads();
    if (tid == 0) out[OFF_FBC] = (float)cnt;
}

// ===== combine / oproj / final =====
__global__ void combine_kernel(const float* __restrict__ sha){
    __shared__ float snm[32];
    if (threadIdx.x < 32) snm[threadIdx.x] = g_nmask[threadIdx.x];
    __syncthreads();
    int idx4 = blockIdx.x*256 + threadIdx.x;
    int d4 = (idx4 & 15) << 2, t = (idx4 >> 4) & (TN-1), b = idx4 >> 15;
    const float* base = sha + ((size_t)(b*TN + t)*MN)*DN + d4;
    const float* w = snm + b*16;
    float4 acc = make_float4(0.f,0.f,0.f,0.f);
    #pragma unroll
    for (int mm = 0; mm < MN; mm++){
        float4 v = *(const float4*)(base + mm*DN);
        float wm = w[mm];
        acc.x = fmaf(v.x,wm,acc.x); acc.y = fmaf(v.y,wm,acc.y);
        acc.z = fmaf(v.z,wm,acc.z); acc.w = fmaf(v.w,wm,acc.w);
    }
    *(float4*)(g_comb + (size_t)idx4*4) = acc;
}
__global__ void oproj_kernel(const float* __restrict__ ow){
    __shared__ float snm[32];
    if (threadIdx.x < 32) snm[threadIdx.x] = g_nmask[threadIdx.x];
    __syncthreads();
    int idx4 = blockIdx.x*256 + threadIdx.x;
    int h4 = (idx4 & 255) << 2, dd = (idx4 >> 8) & 63, b = idx4 >> 14;
    float4 acc = make_float4(0.f,0.f,0.f,0.f);
    #pragma unroll
    for (int mm = 0; mm < MN; mm++){
        float4 v = *(const float4*)(ow + ((size_t)mm*DN + dd)*HN + h4);
        float wm = snm[b*16 + mm];
        acc.x = fmaf(v.x,wm,acc.x); acc.y = fmaf(v.y,wm,acc.y);
        acc.z = fmaf(v.z,wm,acc.z); acc.w = fmaf(v.w,wm,acc.w);
    }
    *(float4*)(g_oproj + (size_t)idx4*4) = acc;
}
__global__ void final_kernel(float* __restrict__ out){
    __shared__ float smem[16*68 + 16*64];
    float* sAt = smem;
    float* sB = smem + 16*68;
    int tid = threadIdx.x;
    int r0 = (tid >> 4) << 2, c0 = (tid & 15) << 2;
    int arow = tid >> 2, ak = (tid & 3) << 2;
    int wkr = tid >> 4, wn = (tid & 15) << 2;
    int ht = blockIdx.x, qt = blockIdx.y, b = blockIdx.z;
    const float* A = g_comb + (size_t)b*TN*DN + (size_t)qt*64*DN;
    const float* W = g_oproj + (size_t)b*DN*HN + ht*64;
    float* C = out + (size_t)b*TN*HN + (size_t)qt*64*HN + ht*64;
    u64 acc2[4][2] = {};
    for (int k0 = 0; k0 < DN; k0 += 16){
        __syncthreads();
        float4 av = *(const float4*)(A + (size_t)arow*DN + k0 + ak);
        sAt[(ak+0)*68+arow]=av.x; sAt[(ak+1)*68+arow]=av.y;
        sAt[(ak+2)*68+arow]=av.z; sAt[(ak+3)*68+arow]=av.w;
        *(float4*)(sB + wkr*64 + wn) = *(const float4*)(W + (size_t)(k0+wkr)*HN + wn);
        __syncthreads();
        #pragma unroll
        for (int kk = 0; kk < 16; kk++){
            float4 a4 = *(const float4*)(sAt + kk*68 + r0);
            ulonglong2 bu = *(const ulonglong2*)(sB + kk*64 + c0);
            u64 a0 = pk2f(a4.x,a4.x), a1 = pk2f(a4.y,a4.y);
            u64 a2 = pk2f(a4.z,a4.z), a3 = pk2f(a4.w,a4.w);
            ffma2(acc2[0][0],a0,bu.x); ffma2(acc2[0][1],a0,bu.y);
            ffma2(acc2[1][0],a1,bu.x); ffma2(acc2[1][1],a1,bu.y);
            ffma2(acc2[2][0],a2,bu.x); ffma2(acc2[2][1],a2,bu.y);
            ffma2(acc2[3][0],a3,bu.x); ffma2(acc2[3][1],a3,bu.y);
        }
    }
    #pragma unroll
    for (int i = 0; i < 4; i++){
        float4 o;
        upk2f(o.x,o.y,acc2[i][0]); upk2f(o.z,o.w,acc2[i][1]);
        *(float4*)(C + (size_t)(r0+i)*HN + c0) = o;
    }
}

extern "C" void kernel_launch(void* const* d_in, const int* in_sizes, int n_in,
                              void* d_out, int out_size)
{
    const float* hs    = (const float*)d_in[0];
    const float* wq    = (const float*)d_in[1];
    const float* wk    = (const float*)d_in[2];
    const float* wv    = (const float*)d_in[3];
    const float* ow    = (const float*)d_in[4];
    const float* gates = (const float*)d_in[5];
    float* out = (float*)d_out;

    cudaFuncSetAttribute(proj_kernel<2>, cudaFuncAttributeMaxDynamicSharedMemorySize, PJ_SMEM);
    cudaFuncSetAttribute(proj_kernel<3>, cudaFuncAttributeMaxDynamicSharedMemorySize, PJ_SMEM);
    cudaFuncSetAttribute(attn_kernel, cudaFuncAttributeMaxDynamicSharedMemorySize, AT_SMEM);

    init_kernel<<<1, 32>>>();
    split_hs_kernel<<<BN*TN, 256>>>(hs);
    split_w_kernel<<<dim3(512, 3), 256>>>(wq, wk, wv);
    proj_kernel<3><<<dim3(16, 16, 2), 128, PJ_SMEM>>>();
    proj_kernel<2><<<dim3(16, 16, 4), 128, PJ_SMEM>>>();
    repack_v_kernel<<<dim3(64, 32), 256>>>();
    attn_kernel<<<dim3(16, 16, 2), 128, AT_SMEM>>>(out + OFF_SHA);
    gate_kernel<<<1, 32>>>(gates, out);
    combine_kernel<<<256, 256>>>(out + OFF_SHA);
    oproj_kernel<<<128, 256>>>(ow);
    final_kernel<<<dim3(16, 32, 2), 256>>>(out);
}